// round 2
// baseline (speedup 1.0000x reference)
#include <cuda_runtime.h>

#define BB 2048
#define C_IN 256
#define L_IN 256
#define C_OUT 64
#define KW 16
#define L_OUT 61
#define FLAT 3904   // 64*61
#define H1 512
#define H2 128

// Scratch (static device arrays; no allocation anywhere)
__device__ float g_act[(size_t)BB * FLAT];   // [b][l*64+co]   (permuted flat layout)
__device__ float g_w12[(size_t)H2 * FLAT];   // [j][l*64+co]   (same permutation)
__device__ float g_b12[H2];
__device__ float g_cw[C_IN * KW * C_OUT];    // [ci][k][co], BN folded
__device__ float g_cb[C_OUT];

// ---------------------------------------------------------------------------
// Fold BN into conv weights/bias, transpose weights to [ci][k][co]
// ---------------------------------------------------------------------------
__global__ void fold_kernel(const float* __restrict__ conv_w,
                            const float* __restrict__ conv_b,
                            const float* __restrict__ gamma,
                            const float* __restrict__ beta,
                            const float* __restrict__ mean,
                            const float* __restrict__ var) {
    int idx = blockIdx.x * blockDim.x + threadIdx.x;
    if (idx < C_IN * KW * C_OUT) {
        int co = idx & 63;
        int k  = (idx >> 6) & 15;
        int ci = idx >> 10;
        float inv = gamma[co] * rsqrtf(var[co] + 1e-5f);
        g_cw[idx] = conv_w[(co * C_IN + ci) * KW + k] * inv;
    }
    if (idx < C_OUT) {
        float inv = gamma[idx] * rsqrtf(var[idx] + 1e-5f);
        g_cb[idx] = (conv_b[idx] - mean[idx]) * inv + beta[idx];
    }
}

// ---------------------------------------------------------------------------
// b12[j] = fc2_b[j] + sum_h fc2_w[j,h] * fc1_b[h]
// ---------------------------------------------------------------------------
__global__ void b12_kernel(const float* __restrict__ fc2_w,
                           const float* __restrict__ fc2_b,
                           const float* __restrict__ fc1_b) {
    int j = threadIdx.x;
    float s = fc2_b[j];
    for (int h = 0; h < H1; h++) s = fmaf(fc2_w[j * H1 + h], fc1_b[h], s);
    g_b12[j] = s;
}

// ---------------------------------------------------------------------------
// W12 = fc2_w @ fc1_w : [128, 3904], stored permuted [j][l*64+co]
// grid 122 blocks (f-tiles of 32), 256 threads
// ---------------------------------------------------------------------------
__global__ void __launch_bounds__(256) w12_kernel(const float* __restrict__ fc1_w,
                                                  const float* __restrict__ fc2_w) {
    __shared__ float s1[32][33];    // fc1 tile [hh][ff]
    __shared__ float s2[32][129];   // fc2 tile transposed [hh][j]
    int t  = threadIdx.x;
    int f0 = blockIdx.x * 32;
    int j  = t & 127;               // lane-consecutive j
    int fg = t >> 7;                // 0/1 -> which 16 f's
    float acc[16];
#pragma unroll
    for (int q = 0; q < 16; q++) acc[q] = 0.f;

    for (int h0 = 0; h0 < H1; h0 += 32) {
        __syncthreads();
#pragma unroll
        for (int r = 0; r < 4; r++) {
            int idx = r * 256 + t;
            int hh = idx >> 5, ff = idx & 31;
            s1[hh][ff] = fc1_w[(size_t)(h0 + hh) * FLAT + f0 + ff];
        }
#pragma unroll
        for (int r = 0; r < 16; r++) {
            int idx = r * 256 + t;
            int jj = idx >> 5, hh = idx & 31;
            s2[hh][jj] = fc2_w[jj * H1 + h0 + hh];
        }
        __syncthreads();
#pragma unroll 4
        for (int hh = 0; hh < 32; hh++) {
            float w2 = s2[hh][j];
#pragma unroll
            for (int q = 0; q < 16; q++)
                acc[q] = fmaf(w2, s1[hh][fg * 16 + q], acc[q]);
        }
    }
#pragma unroll
    for (int q = 0; q < 16; q++) {
        int f = f0 + fg * 16 + q;       // f = co*61 + l (reference flatten order)
        int co = f / L_OUT;
        int l  = f - co * L_OUT;
        g_w12[(size_t)j * FLAT + l * 64 + co] = acc[q];
    }
}

// ---------------------------------------------------------------------------
// Conv + BN + ReLU -> g_act[b][l*64+co]
// One batch per block; 256 threads: co = t&63, l-phase lt = t>>6.
// Thread accumulates 16 l positions (l = lt + 4i).
// ---------------------------------------------------------------------------
__global__ void __launch_bounds__(256) conv_kernel(const float* __restrict__ x) {
    __shared__ float xs[8][272];          // 256 + 16 pad (window overrun for masked l)
    __shared__ float ws[8 * 16 * 64];     // [ci][k][co] chunk
    int b  = blockIdx.x;
    int t  = threadIdx.x;
    int co = t & 63;
    int lt = t >> 6;

    float acc[16];
#pragma unroll
    for (int i = 0; i < 16; i++) acc[i] = 0.f;

    const float* xb = x + (size_t)b * (C_IN * L_IN);

#pragma unroll 1
    for (int c0 = 0; c0 < C_IN; c0 += 8) {
        __syncthreads();
        // stage x chunk: 8 channels x 256
#pragma unroll
        for (int r = 0; r < 8; r++) {
            int idx = r * 256 + t;
            int ci = idx >> 8, pos = idx & 255;
            xs[ci][pos] = xb[(c0 + ci) * L_IN + pos];
        }
        // stage weight chunk: contiguous copy (8*16*64 floats)
        {
            const float4* gw = (const float4*)(g_cw + c0 * (KW * C_OUT));
            float4* wsv = (float4*)ws;
#pragma unroll
            for (int r = 0; r < 8; r++) wsv[r * 256 + t] = gw[r * 256 + t];
        }
        __syncthreads();

#pragma unroll
        for (int ci = 0; ci < 8; ci++) {
            float wr[16];
#pragma unroll
            for (int k = 0; k < 16; k++) wr[k] = ws[(ci * 16 + k) * 64 + co];
#pragma unroll
            for (int i = 0; i < 16; i++) {
                // x window for l = lt+4i starts at element 4*(lt+4i); 16 wide
                const float4* xp = (const float4*)(&xs[ci][0]) + (lt + 4 * i);
                float4 xa = xp[0], xv1 = xp[1], xv2 = xp[2], xv3 = xp[3];
                float a = acc[i];
                a = fmaf(xa.x,  wr[0],  a);  a = fmaf(xa.y,  wr[1],  a);
                a = fmaf(xa.z,  wr[2],  a);  a = fmaf(xa.w,  wr[3],  a);
                a = fmaf(xv1.x, wr[4],  a);  a = fmaf(xv1.y, wr[5],  a);
                a = fmaf(xv1.z, wr[6],  a);  a = fmaf(xv1.w, wr[7],  a);
                a = fmaf(xv2.x, wr[8],  a);  a = fmaf(xv2.y, wr[9],  a);
                a = fmaf(xv2.z, wr[10], a);  a = fmaf(xv2.w, wr[11], a);
                a = fmaf(xv3.x, wr[12], a);  a = fmaf(xv3.y, wr[13], a);
                a = fmaf(xv3.z, wr[14], a);  a = fmaf(xv3.w, wr[15], a);
                acc[i] = a;
            }
        }
    }

    float bias = g_cb[co];
#pragma unroll
    for (int i = 0; i < 16; i++) {
        int l = lt + 4 * i;
        if (l < L_OUT) {
            float v = acc[i] + bias;
            g_act[(size_t)b * FLAT + l * 64 + co] = v > 0.f ? v : 0.f;
        }
    }
}

// ---------------------------------------------------------------------------
// feats = act @ W12^T + b12, then out[b,j,c] = feats*bit_w[j,c] + bit_b[j,c]
// grid 128 blocks (16 b each), 256 threads; thread: 2 b x 4 j
// ---------------------------------------------------------------------------
__global__ void __launch_bounds__(256) feats_kernel(const float* __restrict__ bit_w,
                                                    const float* __restrict__ bit_b,
                                                    float* __restrict__ out) {
    __shared__ float sa[16][33];    // act tile [bb][kk]
    __shared__ float sw[32][129];   // W12 tile transposed [kk][j]
    int t  = threadIdx.x;
    int b0 = blockIdx.x * 16;
    int tx = t & 31;                // j = tx + 32q (lane-consecutive)
    int ty = t >> 5;                // b = b0 + ty*2 + i

    float acc[2][4];
#pragma unroll
    for (int i = 0; i < 2; i++)
#pragma unroll
        for (int q = 0; q < 4; q++) acc[i][q] = 0.f;

#pragma unroll 1
    for (int k0 = 0; k0 < FLAT; k0 += 32) {
        __syncthreads();
#pragma unroll
        for (int r = 0; r < 2; r++) {
            int idx = r * 256 + t;
            int bb = idx >> 5, kk = idx & 31;
            sa[bb][kk] = g_act[(size_t)(b0 + bb) * FLAT + k0 + kk];
        }
#pragma unroll
        for (int r = 0; r < 16; r++) {
            int idx = r * 256 + t;
            int jj = idx >> 5, kk = idx & 31;
            sw[kk][jj] = g_w12[(size_t)jj * FLAT + k0 + kk];
        }
        __syncthreads();
#pragma unroll 4
        for (int kk = 0; kk < 32; kk++) {
            float a0 = sa[ty * 2 + 0][kk];
            float a1 = sa[ty * 2 + 1][kk];
#pragma unroll
            for (int q = 0; q < 4; q++) {
                float w = sw[kk][tx + 32 * q];
                acc[0][q] = fmaf(a0, w, acc[0][q]);
                acc[1][q] = fmaf(a1, w, acc[1][q]);
            }
        }
    }

#pragma unroll
    for (int q = 0; q < 4; q++) {
        int j = tx + 32 * q;
        float bw0 = bit_w[j * 2 + 0], bw1 = bit_w[j * 2 + 1];
        float bb0 = bit_b[j * 2 + 0], bb1 = bit_b[j * 2 + 1];
        float bj  = g_b12[j];
#pragma unroll
        for (int i = 0; i < 2; i++) {
            int b = b0 + ty * 2 + i;
            float f = acc[i][q] + bj;
            size_t o = ((size_t)b * 128 + j) * 2;
            out[o + 0] = fmaf(f, bw0, bb0);
            out[o + 1] = fmaf(f, bw1, bb1);
        }
    }
}

// ---------------------------------------------------------------------------
extern "C" void kernel_launch(void* const* d_in, const int* in_sizes, int n_in,
                              void* d_out, int out_size) {
    const float* x      = (const float*)d_in[0];
    const float* conv_w = (const float*)d_in[1];
    const float* conv_b = (const float*)d_in[2];
    const float* gamma  = (const float*)d_in[3];
    const float* beta   = (const float*)d_in[4];
    const float* mean   = (const float*)d_in[5];
    const float* var    = (const float*)d_in[6];
    const float* fc1_w  = (const float*)d_in[7];
    const float* fc1_b  = (const float*)d_in[8];
    const float* fc2_w  = (const float*)d_in[9];
    const float* fc2_b  = (const float*)d_in[10];
    const float* bit_w  = (const float*)d_in[11];
    const float* bit_b  = (const float*)d_in[12];
    float* out = (float*)d_out;

    fold_kernel<<<(C_IN * KW * C_OUT + 255) / 256, 256>>>(conv_w, conv_b, gamma, beta, mean, var);
    b12_kernel<<<1, H2>>>(fc2_w, fc2_b, fc1_b);
    w12_kernel<<<FLAT / 32, 256>>>(fc1_w, fc2_w);
    conv_kernel<<<BB, 256>>>(x);
    feats_kernel<<<BB / 16, 256>>>(bit_w, bit_b, out);
}

// round 5
// speedup vs baseline: 3.7529x; 3.7529x over previous
#include <cuda_runtime.h>
#include <cstdint>

#define BB 2048
#define C_IN 256
#define L_IN 256
#define C_OUT 64
#define KW 16
#define L_OUT 61
#define FLAT 3904   // 64*61
#define H1 512
#define H2 128
#define KTOT 4096   // C_IN*KW
#define QB 8        // batches per block (1 per warp)
#define NCHUNK 64   // K chunks of 64 (4 ci each)

// ---------------- scratch (static device arrays; no allocation) -------------
__device__ float g_act[(size_t)BB * FLAT];       // [b][l*64+co]
__device__ float g_w12[(size_t)H2 * FLAT];       // [j][l*64+co]
__device__ float g_b12[H2];
__device__ float g_cw[C_IN * KW * C_OUT];        // [ci][k][co], BN folded
__device__ float g_cb[C_OUT];
__device__ unsigned g_wh[C_OUT * (KTOT / 2)];    // fp16x2 pairs, [co][K/2]

// ---------------- PTX helpers ----------------------------------------------
__device__ __forceinline__ uint32_t smem_u32(const void* p) {
    uint32_t a;
    asm("{ .reg .u64 t; cvta.to.shared.u64 t, %1; cvt.u32.u64 %0, t; }"
        : "=r"(a) : "l"(p));
    return a;
}
// pack {low half = lo, high half = hi} as f16x2
__device__ __forceinline__ uint32_t f16pair(float lo, float hi) {
    uint32_t r;
    asm("cvt.rn.f16x2.f32 %0, %1, %2;" : "=r"(r) : "f"(hi), "f"(lo));
    return r;
}
__device__ __forceinline__ void ldsm4(uint32_t* r, uint32_t addr) {
    asm volatile("ldmatrix.sync.aligned.m8n8.x4.shared.b16 {%0,%1,%2,%3}, [%4];"
                 : "=r"(r[0]), "=r"(r[1]), "=r"(r[2]), "=r"(r[3]) : "r"(addr));
}
__device__ __forceinline__ void hmma(float* d, uint32_t a0, uint32_t a1,
                                     uint32_t a2, uint32_t a3,
                                     uint32_t b0, uint32_t b1) {
    asm volatile("mma.sync.aligned.m16n8k16.row.col.f32.f16.f16.f32 "
                 "{%0,%1,%2,%3}, {%4,%5,%6,%7}, {%8,%9}, {%0,%1,%2,%3};"
                 : "+f"(d[0]), "+f"(d[1]), "+f"(d[2]), "+f"(d[3])
                 : "r"(a0), "r"(a1), "r"(a2), "r"(a3), "r"(b0), "r"(b1));
}

// ---------------------------------------------------------------------------
// Fold BN into conv weights/bias, transpose weights to [ci][k][co]
// ---------------------------------------------------------------------------
__global__ void fold_kernel(const float* __restrict__ conv_w,
                            const float* __restrict__ conv_b,
                            const float* __restrict__ gamma,
                            const float* __restrict__ beta,
                            const float* __restrict__ mean,
                            const float* __restrict__ var) {
    int idx = blockIdx.x * blockDim.x + threadIdx.x;
    if (idx < C_IN * KW * C_OUT) {
        int co = idx & 63;
        int k  = (idx >> 6) & 15;
        int ci = idx >> 10;
        float inv = gamma[co] * rsqrtf(var[co] + 1e-5f);
        g_cw[idx] = conv_w[(co * C_IN + ci) * KW + k] * inv;
    }
    if (idx < C_OUT) {
        float inv = gamma[idx] * rsqrtf(var[idx] + 1e-5f);
        g_cb[idx] = (conv_b[idx] - mean[idx]) * inv + beta[idx];
    }
}

// ---------------------------------------------------------------------------
// Convert folded weights to fp16 pairs, K-major [co][K/2]
// ---------------------------------------------------------------------------
__global__ void wcvt_kernel() {
    int idx = blockIdx.x * blockDim.x + threadIdx.x;   // 64*2048
    if (idx >= C_OUT * (KTOT / 2)) return;
    int co = idx >> 11;
    int c2 = idx & 2047;
    int kg = c2 * 2;
    float f0 = g_cw[kg * C_OUT + co];          // g_cw index = (ci*16+k)*64+co = kg*64+co
    float f1 = g_cw[(kg + 1) * C_OUT + co];
    g_wh[idx] = f16pair(f0, f1);
}

// ---------------------------------------------------------------------------
// b12[j] = fc2_b[j] + sum_h fc2_w[j,h] * fc1_b[h]
// ---------------------------------------------------------------------------
__global__ void b12_kernel(const float* __restrict__ fc2_w,
                           const float* __restrict__ fc2_b,
                           const float* __restrict__ fc1_b) {
    int j = threadIdx.x;
    float s = fc2_b[j];
    for (int h = 0; h < H1; h++) s = fmaf(fc2_w[j * H1 + h], fc1_b[h], s);
    g_b12[j] = s;
}

// ---------------------------------------------------------------------------
// W12 = fc2_w @ fc1_w : [128, 3904], stored permuted [j][l*64+co]
// ---------------------------------------------------------------------------
__global__ void __launch_bounds__(256) w12_kernel(const float* __restrict__ fc1_w,
                                                  const float* __restrict__ fc2_w) {
    __shared__ float s1[32][33];
    __shared__ float s2[32][129];
    int t  = threadIdx.x;
    int f0 = blockIdx.x * 32;
    int j  = t & 127;
    int fg = t >> 7;
    float acc[16];
#pragma unroll
    for (int q = 0; q < 16; q++) acc[q] = 0.f;

    for (int h0 = 0; h0 < H1; h0 += 32) {
        __syncthreads();
#pragma unroll
        for (int r = 0; r < 4; r++) {
            int idx = r * 256 + t;
            int hh = idx >> 5, ff = idx & 31;
            s1[hh][ff] = fc1_w[(size_t)(h0 + hh) * FLAT + f0 + ff];
        }
#pragma unroll
        for (int r = 0; r < 16; r++) {
            int idx = r * 256 + t;
            int jj = idx >> 5, hh = idx & 31;
            s2[hh][jj] = fc2_w[jj * H1 + h0 + hh];
        }
        __syncthreads();
#pragma unroll 4
        for (int hh = 0; hh < 32; hh++) {
            float w2 = s2[hh][j];
#pragma unroll
            for (int q = 0; q < 16; q++)
                acc[q] = fmaf(w2, s1[hh][fg * 16 + q], acc[q]);
        }
    }
#pragma unroll
    for (int q = 0; q < 16; q++) {
        int f = f0 + fg * 16 + q;
        int co = f / L_OUT;
        int l  = f - co * L_OUT;
        g_w12[(size_t)j * FLAT + l * 64 + co] = acc[q];
    }
}

// ---------------------------------------------------------------------------
// Conv + BN + ReLU via warp-level mma.sync (fp16 inputs, fp32 accumulate).
// Block: 8 warps, warp = 1 batch. M=64 (61 valid l), N=64 co, K=4096.
// A fragments: LDS.64 window reads from staged fp32 x + cvt to f16x2.
// B fragments: ldmatrix from XOR-swizzled fp16 weight smem.
// ---------------------------------------------------------------------------
#define XROW 260                 // floats per (warp,ci) smem row (256 + 4 pad)
__global__ void __launch_bounds__(256) conv_mma_kernel(const float* __restrict__ x) {
    __shared__ float    xs[QB * 4 * XROW + 32];   // staged fp32 x, padded stride
    __shared__ uint32_t bs[C_OUT * 32];           // fp16x2 weights, swizzled
    __shared__ float    cbs[C_OUT];

    int t = threadIdx.x, w = t >> 5, lane = t & 31;
    if (t < C_OUT) cbs[t] = g_cb[t];
    uint32_t bs_addr = smem_u32(bs);

    int b = blockIdx.x * QB + w;
    const float* xg = x + (size_t)b * (C_IN * L_IN);

    float acc[4][8][4];
#pragma unroll
    for (int mt = 0; mt < 4; mt++)
#pragma unroll
        for (int nt = 0; nt < 8; nt++)
#pragma unroll
            for (int r = 0; r < 4; r++) acc[mt][nt][r] = 0.f;

    // B stage indices (per thread, constant across chunks)
    int sco = t >> 2;                 // 0..63
    int si0 = (t & 3) * 8;            // uint index base within 32-uint row
    char* bsc = (char*)bs;
    uint32_t sb0 = (uint32_t)(sco * 128) + (((uint32_t)(si0 * 4) + 0)  ^ ((sco & 7) << 4));
    uint32_t sb1 = (uint32_t)(sco * 128) + (((uint32_t)(si0 * 4) + 16) ^ ((sco & 7) << 4));

    // B ldsm address components (per thread, per product pair p)
    int btile = lane >> 3;            // 0..3 within x4 grouping
    int brow  = lane & 7;
    uint32_t bbase[4];                // bs_addr + co*128
    uint32_t bkb[4];                  // k-byte offset of this matrix (0 or 16)
    uint32_t bsw[4];                  // swizzle term for this co row
#pragma unroll
    for (int p = 0; p < 4; p++) {
        int co = (2 * p + (btile >> 1)) * 8 + brow;
        bbase[p] = bs_addr + (uint32_t)(co * 128);
        bkb[p]   = (uint32_t)((btile & 1) * 16);
        bsw[p]   = (uint32_t)((co & 7) << 4);
    }

#pragma unroll 1
    for (int cc = 0; cc < NCHUNK; cc++) {
        __syncthreads();
        // ---- stage x: 4 ci x 256 floats for this warp's batch ----
        {
            const float4* src = (const float4*)(xg + cc * 1024);
#pragma unroll
            for (int j = 0; j < 8; j++) {
                int flat = j * 128 + lane * 4;        // float index in 1024-chunk
                int ci   = flat >> 8;
                int off  = flat & 255;
                float4 v = src[j * 32 + lane];
                *(float4*)(&xs[(w * 4 + ci) * XROW + off]) = v;
            }
        }
        // ---- stage B: 64 co x 32 uints (fp16x2), swizzled ----
        {
            const uint4* src = (const uint4*)(g_wh + sco * 2048 + cc * 32 + si0);
            uint4 v0 = src[0], v1 = src[1];
            *(uint4*)(bsc + sb0) = v0;
            *(uint4*)(bsc + sb1) = v1;
        }
        __syncthreads();

#pragma unroll
        for (int ks = 0; ks < 4; ks++) {              // ks = ci within chunk
            uint32_t bfr[16];
#pragma unroll
            for (int p = 0; p < 4; p++) {
                // FIX (R4 bug): k-step offset must be inside the swizzle XOR.
                uint32_t addr = bbase[p] + (((uint32_t)(ks * 32) + bkb[p]) ^ bsw[p]);
                ldsm4(&bfr[4 * p], addr);
            }

            const float* xrow = &xs[(w * 4 + ks) * XROW];
            int c = lane & 3, rq = lane >> 2;
#pragma unroll
            for (int mt = 0; mt < 4; mt++) {
                int e0 = 2 * (mt * 16 + rq) + c;      // float2 index: (4l + 2c)/2
                const float2* xp = (const float2*)xrow;
                float2 v0 = xp[e0];
                float2 v1 = xp[e0 + 16];
                float2 v2 = xp[e0 + 4];
                float2 v3 = xp[e0 + 20];
                uint32_t a0 = f16pair(v0.x, v0.y);
                uint32_t a1 = f16pair(v1.x, v1.y);
                uint32_t a2 = f16pair(v2.x, v2.y);
                uint32_t a3 = f16pair(v3.x, v3.y);
#pragma unroll
                for (int nt = 0; nt < 8; nt++) {
                    int bi = 4 * (nt >> 1) + 2 * (nt & 1);
                    hmma(acc[mt][nt], a0, a1, a2, a3, bfr[bi], bfr[bi + 1]);
                }
            }
        }
    }

    // ---- epilogue: bias + relu + store to g_act[b][l*64+co] ----
    int c = lane & 3, rq = lane >> 2;
    float* dst = g_act + (size_t)b * FLAT;
#pragma unroll
    for (int mt = 0; mt < 4; mt++) {
        int l1 = mt * 16 + rq;
        int l2 = l1 + 8;
#pragma unroll
        for (int nt = 0; nt < 8; nt++) {
            int co0 = nt * 8 + 2 * c;
            float cb0 = cbs[co0], cb1 = cbs[co0 + 1];
            if (l1 < L_OUT) {
                float v0 = acc[mt][nt][0] + cb0;
                float v1 = acc[mt][nt][1] + cb1;
                float2 o = make_float2(v0 > 0.f ? v0 : 0.f, v1 > 0.f ? v1 : 0.f);
                *(float2*)(dst + l1 * 64 + co0) = o;
            }
            if (l2 < L_OUT) {
                float v2 = acc[mt][nt][2] + cb0;
                float v3 = acc[mt][nt][3] + cb1;
                float2 o = make_float2(v2 > 0.f ? v2 : 0.f, v3 > 0.f ? v3 : 0.f);
                *(float2*)(dst + l2 * 64 + co0) = o;
            }
        }
    }
}

// ---------------------------------------------------------------------------
// feats = act @ W12^T + b12, then out[b,j,c] = feats*bit_w[j,c] + bit_b[j,c]
// ---------------------------------------------------------------------------
__global__ void __launch_bounds__(256) feats_kernel(const float* __restrict__ bit_w,
                                                    const float* __restrict__ bit_b,
                                                    float* __restrict__ out) {
    __shared__ float sa[16][33];
    __shared__ float sw[32][129];
    int t  = threadIdx.x;
    int b0 = blockIdx.x * 16;
    int tx = t & 31;
    int ty = t >> 5;

    float acc[2][4];
#pragma unroll
    for (int i = 0; i < 2; i++)
#pragma unroll
        for (int q = 0; q < 4; q++) acc[i][q] = 0.f;

#pragma unroll 1
    for (int k0 = 0; k0 < FLAT; k0 += 32) {
        __syncthreads();
#pragma unroll
        for (int r = 0; r < 2; r++) {
            int idx = r * 256 + t;
            int bb = idx >> 5, kk = idx & 31;
            sa[bb][kk] = g_act[(size_t)(b0 + bb) * FLAT + k0 + kk];
        }
#pragma unroll
        for (int r = 0; r < 16; r++) {
            int idx = r * 256 + t;
            int jj = idx >> 5, kk = idx & 31;
            sw[kk][jj] = g_w12[(size_t)jj * FLAT + k0 + kk];
        }
        __syncthreads();
#pragma unroll 4
        for (int kk = 0; kk < 32; kk++) {
            float a0 = sa[ty * 2 + 0][kk];
            float a1 = sa[ty * 2 + 1][kk];
#pragma unroll
            for (int q = 0; q < 4; q++) {
                float wv = sw[kk][tx + 32 * q];
                acc[0][q] = fmaf(a0, wv, acc[0][q]);
                acc[1][q] = fmaf(a1, wv, acc[1][q]);
            }
        }
    }

#pragma unroll
    for (int q = 0; q < 4; q++) {
        int j = tx + 32 * q;
        float bw0 = bit_w[j * 2 + 0], bw1 = bit_w[j * 2 + 1];
        float bb0 = bit_b[j * 2 + 0], bb1 = bit_b[j * 2 + 1];
        float bj  = g_b12[j];
#pragma unroll
        for (int i = 0; i < 2; i++) {
            int b = b0 + ty * 2 + i;
            float f = acc[i][q] + bj;
            size_t o = ((size_t)b * 128 + j) * 2;
            out[o + 0] = fmaf(f, bw0, bb0);
            out[o + 1] = fmaf(f, bw1, bb1);
        }
    }
}

// ---------------------------------------------------------------------------
extern "C" void kernel_launch(void* const* d_in, const int* in_sizes, int n_in,
                              void* d_out, int out_size) {
    const float* x      = (const float*)d_in[0];
    const float* conv_w = (const float*)d_in[1];
    const float* conv_b = (const float*)d_in[2];
    const float* gamma  = (const float*)d_in[3];
    const float* beta   = (const float*)d_in[4];
    const float* mean   = (const float*)d_in[5];
    const float* var    = (const float*)d_in[6];
    const float* fc1_w  = (const float*)d_in[7];
    const float* fc1_b  = (const float*)d_in[8];
    const float* fc2_w  = (const float*)d_in[9];
    const float* fc2_b  = (const float*)d_in[10];
    const float* bit_w  = (const float*)d_in[11];
    const float* bit_b  = (const float*)d_in[12];
    float* out = (float*)d_out;

    fold_kernel<<<(C_IN * KW * C_OUT + 255) / 256, 256>>>(conv_w, conv_b, gamma, beta, mean, var);
    wcvt_kernel<<<(C_OUT * (KTOT / 2) + 255) / 256, 256>>>();
    b12_kernel<<<1, H2>>>(fc2_w, fc2_b, fc1_b);
    w12_kernel<<<FLAT / 32, 256>>>(fc1_w, fc2_w);
    conv_mma_kernel<<<BB / QB, 256>>>(x);
    feats_kernel<<<BB / 16, 256>>>(bit_w, bit_b, out);
}

// round 6
// speedup vs baseline: 6.1113x; 1.6284x over previous
#include <cuda_runtime.h>
#include <cstdint>

#define BB 2048
#define C_IN 256
#define L_IN 256
#define C_OUT 64
#define KW 16
#define L_OUT 61
#define FLAT 3904    // 64*61
#define FLAT2 1952   // FLAT/2 (f16x2 pairs)
#define H1 512
#define H2 128
#define KTOT 4096    // C_IN*KW
#define QB 8         // batches per block in conv (1 per warp)
#define NCHUNK 64    // conv K chunks of 64 (4 ci each)

// ---------------- scratch (static device arrays; no allocation) -------------
__device__ unsigned g_acth[(size_t)BB * FLAT2];   // act fp16x2, [b][(l*64+co)/2]
__device__ float    g_w12p[2 * H2 * FLAT];        // W12 h-split partials (fp32)
__device__ unsigned g_w12h[H2 * FLAT2];           // W12 fp16x2, [j][(l*64+co)/2]
__device__ float    g_b12[H2];
__device__ float    g_cw[C_IN * KW * C_OUT];      // [ci][k][co], BN folded
__device__ float    g_cb[C_OUT];
__device__ unsigned g_wh[C_OUT * (KTOT / 2)];     // conv weights fp16x2, [co][K/2]

// ---------------- PTX helpers ----------------------------------------------
__device__ __forceinline__ uint32_t smem_u32(const void* p) {
    uint32_t a;
    asm("{ .reg .u64 t; cvta.to.shared.u64 t, %1; cvt.u32.u64 %0, t; }"
        : "=r"(a) : "l"(p));
    return a;
}
// pack {low half = lo, high half = hi} as f16x2
__device__ __forceinline__ uint32_t f16pair(float lo, float hi) {
    uint32_t r;
    asm("cvt.rn.f16x2.f32 %0, %1, %2;" : "=r"(r) : "f"(hi), "f"(lo));
    return r;
}
__device__ __forceinline__ void ldsm4(uint32_t* r, uint32_t addr) {
    asm volatile("ldmatrix.sync.aligned.m8n8.x4.shared.b16 {%0,%1,%2,%3}, [%4];"
                 : "=r"(r[0]), "=r"(r[1]), "=r"(r[2]), "=r"(r[3]) : "r"(addr));
}
__device__ __forceinline__ void hmma(float* d, uint32_t a0, uint32_t a1,
                                     uint32_t a2, uint32_t a3,
                                     uint32_t b0, uint32_t b1) {
    asm volatile("mma.sync.aligned.m16n8k16.row.col.f32.f16.f16.f32 "
                 "{%0,%1,%2,%3}, {%4,%5,%6,%7}, {%8,%9}, {%0,%1,%2,%3};"
                 : "+f"(d[0]), "+f"(d[1]), "+f"(d[2]), "+f"(d[3])
                 : "r"(a0), "r"(a1), "r"(a2), "r"(a3), "r"(b0), "r"(b1));
}

// ---------------------------------------------------------------------------
// Fold BN into conv weights/bias, transpose weights to [ci][k][co]
// ---------------------------------------------------------------------------
__global__ void fold_kernel(const float* __restrict__ conv_w,
                            const float* __restrict__ conv_b,
                            const float* __restrict__ gamma,
                            const float* __restrict__ beta,
                            const float* __restrict__ mean,
                            const float* __restrict__ var) {
    int idx = blockIdx.x * blockDim.x + threadIdx.x;
    if (idx < C_IN * KW * C_OUT) {
        int co = idx & 63;
        int k  = (idx >> 6) & 15;
        int ci = idx >> 10;
        float inv = gamma[co] * rsqrtf(var[co] + 1e-5f);
        g_cw[idx] = conv_w[(co * C_IN + ci) * KW + k] * inv;
    }
    if (idx < C_OUT) {
        float inv = gamma[idx] * rsqrtf(var[idx] + 1e-5f);
        g_cb[idx] = (conv_b[idx] - mean[idx]) * inv + beta[idx];
    }
}

// ---------------------------------------------------------------------------
// Convert folded conv weights to fp16 pairs, K-major [co][K/2]
// ---------------------------------------------------------------------------
__global__ void wcvt_kernel() {
    int idx = blockIdx.x * blockDim.x + threadIdx.x;
    if (idx >= C_OUT * (KTOT / 2)) return;
    int co = idx >> 11;
    int c2 = idx & 2047;
    int kg = c2 * 2;
    float f0 = g_cw[kg * C_OUT + co];
    float f1 = g_cw[(kg + 1) * C_OUT + co];
    g_wh[idx] = f16pair(f0, f1);
}

// ---------------------------------------------------------------------------
// b12[j] = fc2_b[j] + sum_h fc2_w[j,h] * fc1_b[h]
// ---------------------------------------------------------------------------
__global__ void b12_kernel(const float* __restrict__ fc2_w,
                           const float* __restrict__ fc2_b,
                           const float* __restrict__ fc1_b) {
    int j = threadIdx.x;
    float s = fc2_b[j];
    for (int h = 0; h < H1; h++) s = fmaf(fc2_w[j * H1 + h], fc1_b[h], s);
    g_b12[j] = s;
}

// ---------------------------------------------------------------------------
// W12 partial = fc2_w[:, hrange] @ fc1_w[hrange, :], permuted [j][l*64+co].
// grid (122, 2): x = f-tile of 32, y = h-half (256 each).
// ---------------------------------------------------------------------------
__global__ void __launch_bounds__(256) w12p_kernel(const float* __restrict__ fc1_w,
                                                   const float* __restrict__ fc2_w) {
    __shared__ float s1[32][33];
    __shared__ float s2[32][129];
    int t  = threadIdx.x;
    int f0 = blockIdx.x * 32;
    int hb = blockIdx.y * 256;
    int j  = t & 127;
    int fg = t >> 7;
    float acc[16];
#pragma unroll
    for (int q = 0; q < 16; q++) acc[q] = 0.f;

    for (int h0s = 0; h0s < 256; h0s += 32) {
        int h0 = hb + h0s;
        __syncthreads();
#pragma unroll
        for (int r = 0; r < 4; r++) {
            int idx = r * 256 + t;
            int hh = idx >> 5, ff = idx & 31;
            s1[hh][ff] = fc1_w[(size_t)(h0 + hh) * FLAT + f0 + ff];
        }
#pragma unroll
        for (int r = 0; r < 16; r++) {
            int idx = r * 256 + t;
            int jj = idx >> 5, hh = idx & 31;
            s2[hh][jj] = fc2_w[jj * H1 + h0 + hh];
        }
        __syncthreads();
#pragma unroll 4
        for (int hh = 0; hh < 32; hh++) {
            float w2 = s2[hh][j];
#pragma unroll
            for (int q = 0; q < 16; q++)
                acc[q] = fmaf(w2, s1[hh][fg * 16 + q], acc[q]);
        }
    }
    float* dst = g_w12p + (size_t)blockIdx.y * (H2 * FLAT);
#pragma unroll
    for (int q = 0; q < 16; q++) {
        int f = f0 + fg * 16 + q;
        int co = f / L_OUT;
        int l  = f - co * L_OUT;
        dst[(size_t)j * FLAT + l * 64 + co] = acc[q];
    }
}

// ---------------------------------------------------------------------------
// Reduce the two W12 partials and emit fp16 pairs. grid (8, 128).
// ---------------------------------------------------------------------------
__global__ void w12red_kernel() {
    int pi = blockIdx.x * 256 + threadIdx.x;
    if (pi >= FLAT2) return;
    int j = blockIdx.y;
    int lf = pi * 2;
    const float* p0 = g_w12p + (size_t)j * FLAT;
    const float* p1 = p0 + (size_t)H2 * FLAT;
    float v0 = p0[lf] + p1[lf];
    float v1 = p0[lf + 1] + p1[lf + 1];
    g_w12h[(size_t)j * FLAT2 + pi] = f16pair(v0, v1);
}

// ---------------------------------------------------------------------------
// Conv + BN + ReLU via mma.sync (fp16, fp32 accumulate) -> g_acth (fp16).
// ---------------------------------------------------------------------------
#define XROW 260
__global__ void __launch_bounds__(256) conv_mma_kernel(const float* __restrict__ x) {
    __shared__ float    xs[QB * 4 * XROW + 32];
    __shared__ uint32_t bs[C_OUT * 32];
    __shared__ float    cbs[C_OUT];

    int t = threadIdx.x, w = t >> 5, lane = t & 31;
    if (t < C_OUT) cbs[t] = g_cb[t];
    uint32_t bs_addr = smem_u32(bs);

    int b = blockIdx.x * QB + w;
    const float* xg = x + (size_t)b * (C_IN * L_IN);

    float acc[4][8][4];
#pragma unroll
    for (int mt = 0; mt < 4; mt++)
#pragma unroll
        for (int nt = 0; nt < 8; nt++)
#pragma unroll
            for (int r = 0; r < 4; r++) acc[mt][nt][r] = 0.f;

    int sco = t >> 2;
    int si0 = (t & 3) * 8;
    char* bsc = (char*)bs;
    uint32_t sb0 = (uint32_t)(sco * 128) + (((uint32_t)(si0 * 4) + 0)  ^ ((sco & 7) << 4));
    uint32_t sb1 = (uint32_t)(sco * 128) + (((uint32_t)(si0 * 4) + 16) ^ ((sco & 7) << 4));

    int btile = lane >> 3;
    int brow  = lane & 7;
    uint32_t bbase[4], bkb[4], bsw[4];
#pragma unroll
    for (int p = 0; p < 4; p++) {
        int co = (2 * p + (btile >> 1)) * 8 + brow;
        bbase[p] = bs_addr + (uint32_t)(co * 128);
        bkb[p]   = (uint32_t)((btile & 1) * 16);
        bsw[p]   = (uint32_t)((co & 7) << 4);
    }

#pragma unroll 1
    for (int cc = 0; cc < NCHUNK; cc++) {
        __syncthreads();
        {
            const float4* src = (const float4*)(xg + cc * 1024);
#pragma unroll
            for (int j = 0; j < 8; j++) {
                int flat = j * 128 + lane * 4;
                int ci   = flat >> 8;
                int off  = flat & 255;
                float4 v = src[j * 32 + lane];
                *(float4*)(&xs[(w * 4 + ci) * XROW + off]) = v;
            }
        }
        {
            const uint4* src = (const uint4*)(g_wh + sco * 2048 + cc * 32 + si0);
            uint4 v0 = src[0], v1 = src[1];
            *(uint4*)(bsc + sb0) = v0;
            *(uint4*)(bsc + sb1) = v1;
        }
        __syncthreads();

#pragma unroll
        for (int ks = 0; ks < 4; ks++) {
            uint32_t bfr[16];
#pragma unroll
            for (int p = 0; p < 4; p++) {
                uint32_t addr = bbase[p] + (((uint32_t)(ks * 32) + bkb[p]) ^ bsw[p]);
                ldsm4(&bfr[4 * p], addr);
            }

            const float* xrow = &xs[(w * 4 + ks) * XROW];
            int c = lane & 3, rq = lane >> 2;
#pragma unroll
            for (int mt = 0; mt < 4; mt++) {
                int e0 = 2 * (mt * 16 + rq) + c;
                const float2* xp = (const float2*)xrow;
                float2 v0 = xp[e0];
                float2 v1 = xp[e0 + 16];
                float2 v2 = xp[e0 + 4];
                float2 v3 = xp[e0 + 20];
                uint32_t a0 = f16pair(v0.x, v0.y);
                uint32_t a1 = f16pair(v1.x, v1.y);
                uint32_t a2 = f16pair(v2.x, v2.y);
                uint32_t a3 = f16pair(v3.x, v3.y);
#pragma unroll
                for (int nt = 0; nt < 8; nt++) {
                    int bi = 4 * (nt >> 1) + 2 * (nt & 1);
                    hmma(acc[mt][nt], a0, a1, a2, a3, bfr[bi], bfr[bi + 1]);
                }
            }
        }
    }

    // ---- epilogue: bias + relu -> fp16 pairs -> g_acth[b][(l*64+co)/2] ----
    int c = lane & 3, rq = lane >> 2;
    unsigned* dst = g_acth + (size_t)b * FLAT2;
#pragma unroll
    for (int mt = 0; mt < 4; mt++) {
        int l1 = mt * 16 + rq;
        int l2 = l1 + 8;
#pragma unroll
        for (int nt = 0; nt < 8; nt++) {
            int co0 = nt * 8 + 2 * c;
            float cb0 = cbs[co0], cb1 = cbs[co0 + 1];
            if (l1 < L_OUT) {
                float v0 = acc[mt][nt][0] + cb0;
                float v1 = acc[mt][nt][1] + cb1;
                dst[l1 * 32 + nt * 4 + c] =
                    f16pair(v0 > 0.f ? v0 : 0.f, v1 > 0.f ? v1 : 0.f);
            }
            if (l2 < L_OUT) {
                float v2 = acc[mt][nt][2] + cb0;
                float v3 = acc[mt][nt][3] + cb1;
                dst[l2 * 32 + nt * 4 + c] =
                    f16pair(v2 > 0.f ? v2 : 0.f, v3 > 0.f ? v3 : 0.f);
            }
        }
    }
}

// ---------------------------------------------------------------------------
// feats = act @ W12^T + b12 via mma.sync, fused parabit heads -> out.
// grid 64: M-tile 32 batches. Block 256 thr: warps 2m x 4j; warp m16 x j32.
// K = 3904 in 61 chunks of 64.
// ---------------------------------------------------------------------------
__global__ void __launch_bounds__(256) feats_mma_kernel(const float* __restrict__ bit_w,
                                                        const float* __restrict__ bit_b,
                                                        float* __restrict__ out) {
    __shared__ uint32_t as_[32 * 32];     // A tile: 32 rows x 128B, swizzled
    __shared__ uint32_t ws_[H2 * 32];     // B tile: 128 rows x 128B, swizzled
    __shared__ float sb12[H2], sbw[H2 * 2], sbb[H2 * 2];

    int t = threadIdx.x, w = t >> 5, lane = t & 31;
    int mw = w >> 2, jw = w & 3;
    if (t < H2) sb12[t] = g_b12[t];
    if (t < H2 * 2) { sbw[t] = bit_w[t]; sbb[t] = bit_b[t]; }
    uint32_t as_addr = smem_u32(as_);
    uint32_t ws_addr = smem_u32(ws_);

    int b0 = blockIdx.x * 32;

    float acc[4][4];
#pragma unroll
    for (int nt = 0; nt < 4; nt++)
#pragma unroll
        for (int r = 0; r < 4; r++) acc[nt][r] = 0.f;

    // A ldmatrix addressing (x4: m0-7/k0, m8-15/k0, m0-7/k8, m8-15/k8)
    int sub = lane >> 3, r8 = lane & 7;
    int arow = mw * 16 + (sub & 1) * 8 + r8;
    uint32_t akb  = (uint32_t)((sub >> 1) * 16);
    uint32_t abase = as_addr + (uint32_t)(arow * 128);
    uint32_t aswz = (uint32_t)(r8 << 4);

    // B ldmatrix addressing (conv-proven pattern, 2 x ldsm.x4 for 32 j)
    int btile = lane >> 3, brow = lane & 7;
    uint32_t bbase[2];
    uint32_t bkb = (uint32_t)((btile & 1) * 16);
    uint32_t bswz = (uint32_t)(brow << 4);
#pragma unroll
    for (int p = 0; p < 2; p++) {
        int jloc = (2 * p + (btile >> 1)) * 8 + brow;
        bbase[p] = ws_addr + (uint32_t)((jw * 32 + jloc) * 128);
    }

    // Stage indices
    int am  = t >> 3;           // A row 0..31
    int akg = t & 7;            // A 16B group
    uint32_t ast = as_addr + (uint32_t)(am * 128) + (((uint32_t)(akg * 16)) ^ ((uint32_t)((am & 7) << 4)));
    int wj  = t >> 1;           // B row 0..127
    int wh  = t & 1;            // B half
    char* wrow = (char*)ws_ + wj * 128;
    uint32_t wswz = (uint32_t)((wj & 7) << 4);

#pragma unroll 1
    for (int cc = 0; cc < 61; cc++) {
        __syncthreads();
        // A: 32 rows x 32 uints from g_acth
        {
            uint4 v = *(const uint4*)(g_acth + (size_t)(b0 + am) * FLAT2 + cc * 32 + akg * 4);
            *(uint4*)((char*)as_ + (ast - as_addr)) = v;
        }
        // B: 128 rows x 32 uints from g_w12h
        {
            const uint4* src = (const uint4*)(g_w12h + (size_t)wj * FLAT2 + cc * 32 + wh * 16);
#pragma unroll
            for (int q = 0; q < 4; q++) {
                uint4 v = src[q];
                *(uint4*)(wrow + (((uint32_t)(wh * 64 + q * 16)) ^ wswz)) = v;
            }
        }
        __syncthreads();

#pragma unroll
        for (int ks = 0; ks < 4; ks++) {
            uint32_t af[4];
            ldsm4(af, abase + (((uint32_t)(ks * 32) + akb) ^ aswz));
            uint32_t bf[8];
#pragma unroll
            for (int p = 0; p < 2; p++)
                ldsm4(&bf[4 * p], bbase[p] + (((uint32_t)(ks * 32) + bkb) ^ bswz));
#pragma unroll
            for (int nt = 0; nt < 4; nt++) {
                int bi = 4 * (nt >> 1) + 2 * (nt & 1);
                hmma(acc[nt], af[0], af[1], af[2], af[3], bf[bi], bf[bi + 1]);
            }
        }
    }

    // ---- epilogue: + b12, parabit heads, write out ----
    int r = lane >> 2, c = lane & 3;
#pragma unroll
    for (int nt = 0; nt < 4; nt++) {
        int j0 = jw * 32 + nt * 8 + 2 * c;
        float bj0 = sb12[j0], bj1 = sb12[j0 + 1];
        float bw00 = sbw[j0 * 2], bw01 = sbw[j0 * 2 + 1];
        float bw10 = sbw[j0 * 2 + 2], bw11 = sbw[j0 * 2 + 3];
        float bb00 = sbb[j0 * 2], bb01 = sbb[j0 * 2 + 1];
        float bb10 = sbb[j0 * 2 + 2], bb11 = sbb[j0 * 2 + 3];
        {
            int b = b0 + mw * 16 + r;
            float f0 = acc[nt][0] + bj0;
            float f1 = acc[nt][1] + bj1;
            float4 o = make_float4(fmaf(f0, bw00, bb00), fmaf(f0, bw01, bb01),
                                   fmaf(f1, bw10, bb10), fmaf(f1, bw11, bb11));
            *(float4*)(out + ((size_t)b * H2 + j0) * 2) = o;
        }
        {
            int b = b0 + mw * 16 + r + 8;
            float f2 = acc[nt][2] + bj0;
            float f3 = acc[nt][3] + bj1;
            float4 o = make_float4(fmaf(f2, bw00, bb00), fmaf(f2, bw01, bb01),
                                   fmaf(f3, bw10, bb10), fmaf(f3, bw11, bb11));
            *(float4*)(out + ((size_t)b * H2 + j0) * 2) = o;
        }
    }
}

// ---------------------------------------------------------------------------
extern "C" void kernel_launch(void* const* d_in, const int* in_sizes, int n_in,
                              void* d_out, int out_size) {
    const float* x      = (const float*)d_in[0];
    const float* conv_w = (const float*)d_in[1];
    const float* conv_b = (const float*)d_in[2];
    const float* gamma  = (const float*)d_in[3];
    const float* beta   = (const float*)d_in[4];
    const float* mean   = (const float*)d_in[5];
    const float* var    = (const float*)d_in[6];
    const float* fc1_w  = (const float*)d_in[7];
    const float* fc1_b  = (const float*)d_in[8];
    const float* fc2_w  = (const float*)d_in[9];
    const float* fc2_b  = (const float*)d_in[10];
    const float* bit_w  = (const float*)d_in[11];
    const float* bit_b  = (const float*)d_in[12];
    float* out = (float*)d_out;

    fold_kernel<<<(C_IN * KW * C_OUT + 255) / 256, 256>>>(conv_w, conv_b, gamma, beta, mean, var);
    wcvt_kernel<<<(C_OUT * (KTOT / 2) + 255) / 256, 256>>>();
    b12_kernel<<<1, H2>>>(fc2_w, fc2_b, fc1_b);
    w12p_kernel<<<dim3(FLAT / 32, 2), 256>>>(fc1_w, fc2_w);
    w12red_kernel<<<dim3((FLAT2 + 255) / 256, H2), 256>>>();
    conv_mma_kernel<<<BB / QB, 256>>>(x);
    feats_mma_kernel<<<BB / 32, 256>>>(bit_w, bit_b, out);
}

// round 8
// speedup vs baseline: 7.2591x; 1.1878x over previous
#include <cuda_runtime.h>
#include <cstdint>

#define BB 2048
#define C_IN 256
#define L_IN 256
#define C_OUT 64
#define KW 16
#define L_OUT 61
#define FLAT 3904    // 64*61
#define FLAT2 1952   // FLAT/2 (f16x2 pairs)
#define H1 512
#define H2 128
#define KTOT 4096    // C_IN*KW
#define NCHUNK 64    // conv K chunks of 64 (4 ci each)

// ---------------- scratch (static device arrays; no allocation) -------------
__device__ unsigned g_acth[(size_t)BB * FLAT2];   // act fp16x2, [b][(l*64+co)/2]
__device__ float    g_w12p[4 * H2 * FLAT];        // W12 h-split partials (fp32)
__device__ unsigned g_w12h[H2 * FLAT2];           // W12 fp16x2, [j][(l*64+co)/2]
__device__ float    g_b12[H2];
__device__ float    g_cw[C_IN * KW * C_OUT];      // [ci][k][co], BN folded
__device__ float    g_cb[C_OUT];
__device__ unsigned g_wh[C_OUT * (KTOT / 2)];     // conv weights fp16x2, [co][K/2]

// ---------------- PTX helpers ----------------------------------------------
__device__ __forceinline__ uint32_t smem_u32(const void* p) {
    uint32_t a;
    asm("{ .reg .u64 t; cvta.to.shared.u64 t, %1; cvt.u32.u64 %0, t; }"
        : "=r"(a) : "l"(p));
    return a;
}
__device__ __forceinline__ uint32_t f16pair(float lo, float hi) {
    uint32_t r;
    asm("cvt.rn.f16x2.f32 %0, %1, %2;" : "=r"(r) : "f"(hi), "f"(lo));
    return r;
}
__device__ __forceinline__ void ldsm4(uint32_t* r, uint32_t addr) {
    asm volatile("ldmatrix.sync.aligned.m8n8.x4.shared.b16 {%0,%1,%2,%3}, [%4];"
                 : "=r"(r[0]), "=r"(r[1]), "=r"(r[2]), "=r"(r[3]) : "r"(addr));
}
__device__ __forceinline__ void hmma(float* d, uint32_t a0, uint32_t a1,
                                     uint32_t a2, uint32_t a3,
                                     uint32_t b0, uint32_t b1) {
    asm volatile("mma.sync.aligned.m16n8k16.row.col.f32.f16.f16.f32 "
                 "{%0,%1,%2,%3}, {%4,%5,%6,%7}, {%8,%9}, {%0,%1,%2,%3};"
                 : "+f"(d[0]), "+f"(d[1]), "+f"(d[2]), "+f"(d[3])
                 : "r"(a0), "r"(a1), "r"(a2), "r"(a3), "r"(b0), "r"(b1));
}
#define CP_ASYNC16(dst, src) \
    asm volatile("cp.async.cg.shared.global [%0], [%1], 16;" \
                 :: "r"(dst), "l"(src) : "memory")
#define CP_COMMIT() asm volatile("cp.async.commit_group;" ::: "memory")
#define CP_WAIT1()  asm volatile("cp.async.wait_group 1;" ::: "memory")

// ---------------------------------------------------------------------------
// Fold BN into conv weights/bias, transpose weights to [ci][k][co]
// ---------------------------------------------------------------------------
__global__ void fold_kernel(const float* __restrict__ conv_w,
                            const float* __restrict__ conv_b,
                            const float* __restrict__ gamma,
                            const float* __restrict__ beta,
                            const float* __restrict__ mean,
                            const float* __restrict__ var) {
    int idx = blockIdx.x * blockDim.x + threadIdx.x;
    if (idx < C_IN * KW * C_OUT) {
        int co = idx & 63;
        int k  = (idx >> 6) & 15;
        int ci = idx >> 10;
        float inv = gamma[co] * rsqrtf(var[co] + 1e-5f);
        g_cw[idx] = conv_w[(co * C_IN + ci) * KW + k] * inv;
    }
    if (idx < C_OUT) {
        float inv = gamma[idx] * rsqrtf(var[idx] + 1e-5f);
        g_cb[idx] = (conv_b[idx] - mean[idx]) * inv + beta[idx];
    }
}

// ---------------------------------------------------------------------------
// Convert folded conv weights to fp16 pairs, K-major [co][K/2]
// ---------------------------------------------------------------------------
__global__ void wcvt_kernel() {
    int idx = blockIdx.x * blockDim.x + threadIdx.x;
    if (idx >= C_OUT * (KTOT / 2)) return;
    int co = idx >> 11;
    int c2 = idx & 2047;
    int kg = c2 * 2;
    float f0 = g_cw[kg * C_OUT + co];
    float f1 = g_cw[(kg + 1) * C_OUT + co];
    g_wh[idx] = f16pair(f0, f1);
}

// ---------------------------------------------------------------------------
// b12[j] = fc2_b[j] + sum_h fc2_w[j,h] * fc1_b[h]
// ---------------------------------------------------------------------------
__global__ void b12_kernel(const float* __restrict__ fc2_w,
                           const float* __restrict__ fc2_b,
                           const float* __restrict__ fc1_b) {
    int j = threadIdx.x;
    float s = fc2_b[j];
    for (int h = 0; h < H1; h++) s = fmaf(fc2_w[j * H1 + h], fc1_b[h], s);
    g_b12[j] = s;
}

// ---------------------------------------------------------------------------
// W12 partial = fc2_w[:, hrange] @ fc1_w[hrange, :], permuted [j][l*64+co].
// grid (122, 4): x = f-tile of 32, y = h-quarter (128 each).
// ---------------------------------------------------------------------------
__global__ void __launch_bounds__(256) w12p_kernel(const float* __restrict__ fc1_w,
                                                   const float* __restrict__ fc2_w) {
    __shared__ float s1[32][33];
    __shared__ float s2[32][129];
    int t  = threadIdx.x;
    int f0 = blockIdx.x * 32;
    int hb = blockIdx.y * 128;
    int j  = t & 127;
    int fg = t >> 7;
    float acc[16];
#pragma unroll
    for (int q = 0; q < 16; q++) acc[q] = 0.f;

    for (int h0s = 0; h0s < 128; h0s += 32) {
        int h0 = hb + h0s;
        __syncthreads();
#pragma unroll
        for (int r = 0; r < 4; r++) {
            int idx = r * 256 + t;
            int hh = idx >> 5, ff = idx & 31;
            s1[hh][ff] = fc1_w[(size_t)(h0 + hh) * FLAT + f0 + ff];
        }
#pragma unroll
        for (int r = 0; r < 16; r++) {
            int idx = r * 256 + t;
            int jj = idx >> 5, hh = idx & 31;
            s2[hh][jj] = fc2_w[jj * H1 + h0 + hh];
        }
        __syncthreads();
#pragma unroll 4
        for (int hh = 0; hh < 32; hh++) {
            float w2 = s2[hh][j];
#pragma unroll
            for (int q = 0; q < 16; q++)
                acc[q] = fmaf(w2, s1[hh][fg * 16 + q], acc[q]);
        }
    }
    float* dst = g_w12p + (size_t)blockIdx.y * (H2 * FLAT);
#pragma unroll
    for (int q = 0; q < 16; q++) {
        int f = f0 + fg * 16 + q;
        int co = f / L_OUT;
        int l  = f - co * L_OUT;
        dst[(size_t)j * FLAT + l * 64 + co] = acc[q];
    }
}

// ---------------------------------------------------------------------------
// Reduce the four W12 partials and emit fp16 pairs. grid (8, 128).
// ---------------------------------------------------------------------------
__global__ void w12red_kernel() {
    int pi = blockIdx.x * 256 + threadIdx.x;
    if (pi >= FLAT2) return;
    int j = blockIdx.y;
    int lf = pi * 2;
    const float* p0 = g_w12p + (size_t)j * FLAT;
    const size_t step = (size_t)H2 * FLAT;
    float v0 = p0[lf] + p0[lf + step] + p0[lf + 2 * step] + p0[lf + 3 * step];
    float v1 = p0[lf + 1] + p0[lf + 1 + step] + p0[lf + 1 + 2 * step] + p0[lf + 1 + 3 * step];
    g_w12h[(size_t)j * FLAT2 + pi] = f16pair(v0, v1);
}

// ---------------------------------------------------------------------------
// Conv + BN + ReLU via mma.sync, cp.async double-buffered pipeline.
// Block: 256 thr / 8 warps, 2 batches. Warp = m16 tile (quarter of a batch),
// all 64 co. grid 1024.
// ---------------------------------------------------------------------------
#define XROWF 260                 // floats per (q,ci) smem row
#define XBUF  2120                // floats per x buffer (8*260 + 40 tail)
__global__ void __launch_bounds__(256) conv_mma_kernel(const float* __restrict__ x) {
    __shared__ float    xs[2][XBUF];         // fp32 x, [buf][(q*4+ci)*260 + pos]
    __shared__ uint32_t bsm[2][C_OUT * 32];  // fp16x2 weights, swizzled
    __shared__ float    cbs[C_OUT];

    int t = threadIdx.x, w = t >> 5, lane = t & 31;
    int q = w >> 2, quarter = w & 3;
    if (t < C_OUT) cbs[t] = g_cb[t];
    uint32_t xs_addr = smem_u32(xs);
    uint32_t bs_addr = smem_u32(bsm);

    int b = blockIdx.x * 2 + q;

    float acc[8][4];
#pragma unroll
    for (int nt = 0; nt < 8; nt++)
#pragma unroll
        for (int r = 0; r < 4; r++) acc[nt][r] = 0.f;

    // ---- B ldmatrix addressing (within-buffer offsets) ----
    int btile = lane >> 3, brow = lane & 7;
    uint32_t bbase[4], bkb[4], bsw[4];
#pragma unroll
    for (int p = 0; p < 4; p++) {
        int co = (2 * p + (btile >> 1)) * 8 + brow;
        bbase[p] = (uint32_t)(co * 128);
        bkb[p]   = (uint32_t)((btile & 1) * 16);
        bsw[p]   = (uint32_t)((co & 7) << 4);
    }

    // ---- staging addressing (per thread, 2 x-chunks + 2 B-chunks) ----
    int xci  = (t >> 6) & 3;                 // ci row
    int xoff = (t & 63) * 16;                // byte offset within 1KB row
    uint32_t xd0 = xs_addr + (uint32_t)(xci * (XROWF * 4)) + (uint32_t)xoff;
    uint32_t xd1 = xd0 + 4 * (XROWF * 4);
    const char* xsrc0 = (const char*)x + (size_t)(blockIdx.x * 2) * (C_IN * L_IN * 4)
                        + xci * 1024 + xoff;
    const char* xsrc1 = xsrc0 + (size_t)(C_IN * L_IN * 4);

    int brw = t >> 3;                        // B rows brw, brw+32
    int bg  = t & 7;
    uint32_t bd0 = bs_addr + (uint32_t)(brw * 128) + (((uint32_t)(bg * 16)) ^ ((uint32_t)((brw & 7) << 4)));
    uint32_t bd1 = bs_addr + (uint32_t)((brw + 32) * 128) + (((uint32_t)(bg * 16)) ^ ((uint32_t)(((brw + 32) & 7) << 4)));
    const char* bsrc0 = (const char*)g_wh + (size_t)brw * 8192 + bg * 16;
    const char* bsrc1 = bsrc0 + (size_t)32 * 8192;

#define STAGE(cc, buf) do {                                                     \
    uint32_t xb = (uint32_t)((buf) * (XBUF * 4));                               \
    uint32_t bb = (uint32_t)((buf) * (C_OUT * 32 * 4));                         \
    size_t xo = (size_t)(cc) * 4096;                                            \
    size_t bo = (size_t)(cc) * 128;                                             \
    CP_ASYNC16(xd0 + xb, xsrc0 + xo);                                           \
    CP_ASYNC16(xd1 + xb, xsrc1 + xo);                                           \
    CP_ASYNC16(bd0 + bb, bsrc0 + bo);                                           \
    CP_ASYNC16(bd1 + bb, bsrc1 + bo);                                           \
} while (0)

    STAGE(0, 0);
    CP_COMMIT();

    int c = lane & 3, rq = lane >> 2;
    int lbase = quarter * 16;

#pragma unroll 1
    for (int cc = 0; cc < NCHUNK; cc++) {
        __syncthreads();                     // prior compute done before overwrite
        if (cc < NCHUNK - 1) STAGE(cc + 1, (cc + 1) & 1);
        CP_COMMIT();
        CP_WAIT1();                          // chunk cc landed
        __syncthreads();

        int buf = cc & 1;
        uint32_t bbuf = bs_addr + (uint32_t)(buf * (C_OUT * 32 * 4));
        const float* xbuf = &xs[buf][q * 4 * XROWF];

#pragma unroll
        for (int ks = 0; ks < 4; ks++) {
            uint32_t bfr[16];
#pragma unroll
            for (int p = 0; p < 4; p++) {
                uint32_t addr = bbuf + bbase[p] + (((uint32_t)(ks * 32) + bkb[p]) ^ bsw[p]);
                ldsm4(&bfr[4 * p], addr);
            }
            const float2* xp = (const float2*)(xbuf + ks * XROWF);
            int e0 = 2 * (lbase + rq) + c;
            float2 v0 = xp[e0];
            float2 v1 = xp[e0 + 16];
            float2 v2 = xp[e0 + 4];
            float2 v3 = xp[e0 + 20];
            uint32_t a0 = f16pair(v0.x, v0.y);
            uint32_t a1 = f16pair(v1.x, v1.y);
            uint32_t a2 = f16pair(v2.x, v2.y);
            uint32_t a3 = f16pair(v3.x, v3.y);
#pragma unroll
            for (int nt = 0; nt < 8; nt++) {
                int bi = 4 * (nt >> 1) + 2 * (nt & 1);
                hmma(acc[nt], a0, a1, a2, a3, bfr[bi], bfr[bi + 1]);
            }
        }
    }

    // ---- epilogue: bias + relu -> fp16 pairs -> g_acth[b][(l*64+co)/2] ----
    unsigned* dst = g_acth + (size_t)b * FLAT2;
    int l1 = lbase + rq;
    int l2 = l1 + 8;
#pragma unroll
    for (int nt = 0; nt < 8; nt++) {
        int co0 = nt * 8 + 2 * c;
        float cb0 = cbs[co0], cb1 = cbs[co0 + 1];
        if (l1 < L_OUT) {
            float v0 = acc[nt][0] + cb0;
            float v1 = acc[nt][1] + cb1;
            dst[l1 * 32 + nt * 4 + c] = f16pair(v0 > 0.f ? v0 : 0.f, v1 > 0.f ? v1 : 0.f);
        }
        if (l2 < L_OUT) {
            float v2 = acc[nt][2] + cb0;
            float v3 = acc[nt][3] + cb1;
            dst[l2 * 32 + nt * 4 + c] = f16pair(v2 > 0.f ? v2 : 0.f, v3 > 0.f ? v3 : 0.f);
        }
    }
#undef STAGE
}

// ---------------------------------------------------------------------------
// feats = act @ W12^T + b12 via mma.sync, fused parabit heads -> out.
// ---------------------------------------------------------------------------
__global__ void __launch_bounds__(256) feats_mma_kernel(const float* __restrict__ bit_w,
                                                        const float* __restrict__ bit_b,
                                                        float* __restrict__ out) {
    __shared__ uint32_t as_[32 * 32];
    __shared__ uint32_t ws_[H2 * 32];
    __shared__ float sb12[H2], sbw[H2 * 2], sbb[H2 * 2];

    int t = threadIdx.x, w = t >> 5, lane = t & 31;
    int mw = w >> 2, jw = w & 3;
    if (t < H2) sb12[t] = g_b12[t];
    if (t < H2 * 2) { sbw[t] = bit_w[t]; sbb[t] = bit_b[t]; }
    uint32_t as_addr = smem_u32(as_);
    uint32_t ws_addr = smem_u32(ws_);

    int b0 = blockIdx.x * 32;

    float acc[4][4];
#pragma unroll
    for (int nt = 0; nt < 4; nt++)
#pragma unroll
        for (int r = 0; r < 4; r++) acc[nt][r] = 0.f;

    int sub = lane >> 3, r8 = lane & 7;
    int arow = mw * 16 + (sub & 1) * 8 + r8;
    uint32_t akb  = (uint32_t)((sub >> 1) * 16);
    uint32_t abase = as_addr + (uint32_t)(arow * 128);
    uint32_t aswz = (uint32_t)(r8 << 4);

    int btile = lane >> 3, brow = lane & 7;
    uint32_t bbase[2];
    uint32_t bkb = (uint32_t)((btile & 1) * 16);
    uint32_t bswz = (uint32_t)(brow << 4);
#pragma unroll
    for (int p = 0; p < 2; p++) {
        int jloc = (2 * p + (btile >> 1)) * 8 + brow;
        bbase[p] = ws_addr + (uint32_t)((jw * 32 + jloc) * 128);
    }

    int am  = t >> 3;
    int akg = t & 7;
    uint32_t ast = as_addr + (uint32_t)(am * 128) + (((uint32_t)(akg * 16)) ^ ((uint32_t)((am & 7) << 4)));
    int wj  = t >> 1;
    int wh  = t & 1;
    char* wrow = (char*)ws_ + wj * 128;
    uint32_t wswz = (uint32_t)((wj & 7) << 4);

#pragma unroll 1
    for (int cc = 0; cc < 61; cc++) {
        __syncthreads();
        {
            uint4 v = *(const uint4*)(g_acth + (size_t)(b0 + am) * FLAT2 + cc * 32 + akg * 4);
            *(uint4*)((char*)as_ + (ast - as_addr)) = v;
        }
        {
            const uint4* src = (const uint4*)(g_w12h + (size_t)wj * FLAT2 + cc * 32 + wh * 16);
#pragma unroll
            for (int qq = 0; qq < 4; qq++) {
                uint4 v = src[qq];
                *(uint4*)(wrow + (((uint32_t)(wh * 64 + qq * 16)) ^ wswz)) = v;
            }
        }
        __syncthreads();

#pragma unroll
        for (int ks = 0; ks < 4; ks++) {
            uint32_t af[4];
            ldsm4(af, abase + (((uint32_t)(ks * 32) + akb) ^ aswz));
            uint32_t bf[8];
#pragma unroll
            for (int p = 0; p < 2; p++)
                ldsm4(&bf[4 * p], bbase[p] + (((uint32_t)(ks * 32) + bkb) ^ bswz));
#pragma unroll
            for (int nt = 0; nt < 4; nt++) {
                int bi = 4 * (nt >> 1) + 2 * (nt & 1);
                hmma(acc[nt], af[0], af[1], af[2], af[3], bf[bi], bf[bi + 1]);
            }
        }
    }

    int r = lane >> 2, c = lane & 3;
#pragma unroll
    for (int nt = 0; nt < 4; nt++) {
        int j0 = jw * 32 + nt * 8 + 2 * c;
        float bj0 = sb12[j0], bj1 = sb12[j0 + 1];
        float bw00 = sbw[j0 * 2], bw01 = sbw[j0 * 2 + 1];
        float bw10 = sbw[j0 * 2 + 2], bw11 = sbw[j0 * 2 + 3];
        float bb00 = sbb[j0 * 2], bb01 = sbb[j0 * 2 + 1];
        float bb10 = sbb[j0 * 2 + 2], bb11 = sbb[j0 * 2 + 3];
        {
            int b = b0 + mw * 16 + r;
            float f0 = acc[nt][0] + bj0;
            float f1 = acc[nt][1] + bj1;
            float4 o = make_float4(fmaf(f0, bw00, bb00), fmaf(f0, bw01, bb01),
                                   fmaf(f1, bw10, bb10), fmaf(f1, bw11, bb11));
            *(float4*)(out + ((size_t)b * H2 + j0) * 2) = o;
        }
        {
            int b = b0 + mw * 16 + r + 8;
            float f2 = acc[nt][2] + bj0;
            float f3 = acc[nt][3] + bj1;
            float4 o = make_float4(fmaf(f2, bw00, bb00), fmaf(f2, bw01, bb01),
                                   fmaf(f3, bw10, bb10), fmaf(f3, bw11, bb11));
            *(float4*)(out + ((size_t)b * H2 + j0) * 2) = o;
        }
    }
}

// ---------------------------------------------------------------------------
extern "C" void kernel_launch(void* const* d_in, const int* in_sizes, int n_in,
                              void* d_out, int out_size) {
    const float* x      = (const float*)d_in[0];
    const float* conv_w = (const float*)d_in[1];
    const float* conv_b = (const float*)d_in[2];
    const float* gamma  = (const float*)d_in[3];
    const float* beta   = (const float*)d_in[4];
    const float* mean   = (const float*)d_in[5];
    const float* var    = (const float*)d_in[6];
    const float* fc1_w  = (const float*)d_in[7];
    const float* fc1_b  = (const float*)d_in[8];
    const float* fc2_w  = (const float*)d_in[9];
    const float* fc2_b  = (const float*)d_in[10];
    const float* bit_w  = (const float*)d_in[11];
    const float* bit_b  = (const float*)d_in[12];
    float* out = (float*)d_out;

    fold_kernel<<<(C_IN * KW * C_OUT + 255) / 256, 256>>>(conv_w, conv_b, gamma, beta, mean, var);
    wcvt_kernel<<<(C_OUT * (KTOT / 2) + 255) / 256, 256>>>();
    b12_kernel<<<1, H2>>>(fc2_w, fc2_b, fc1_b);
    w12p_kernel<<<dim3(FLAT / 32, 4), 256>>>(fc1_w, fc2_w);
    w12red_kernel<<<dim3((FLAT2 + 255) / 256, H2), 256>>>();
    conv_mma_kernel<<<BB / 2, 256>>>(x);
    feats_mma_kernel<<<BB / 32, 256>>>(bit_w, bit_b, out);
}

// round 9
// speedup vs baseline: 7.8766x; 1.0851x over previous
#include <cuda_runtime.h>
#include <cstdint>

#define BB 2048
#define C_IN 256
#define L_IN 256
#define C_OUT 64
#define KW 16
#define L_OUT 61
#define FLAT 3904    // 64*61
#define FLAT2 1952   // FLAT/2 (f16x2 pairs)
#define H1 512
#define H12 256      // H1/2 pairs
#define H2 128
#define KTOT 4096    // C_IN*KW
#define NCHUNK 64    // conv K chunks of 64 (4 ci each)

// ---------------- scratch (static device arrays; no allocation) -------------
__device__ unsigned g_acth[(size_t)BB * FLAT2];   // act fp16x2, [b][(l*64+co)/2]
__device__ unsigned g_w12h[H2 * FLAT2];           // W12 fp16x2, [j][(l*64+co)/2]
__device__ float    g_b12[H2];
__device__ float    g_cb[C_OUT];
__device__ unsigned g_wh[C_OUT * (KTOT / 2)];     // conv weights fp16x2, [co][K/2]
__device__ unsigned g_f1h[(size_t)FLAT * H12];    // fc1^T fp16x2, [f][h/2]
__device__ unsigned g_f2h[H2 * H12];              // fc2 fp16x2, [j][h/2]

// ---------------- PTX helpers ----------------------------------------------
__device__ __forceinline__ uint32_t smem_u32(const void* p) {
    uint32_t a;
    asm("{ .reg .u64 t; cvta.to.shared.u64 t, %1; cvt.u32.u64 %0, t; }"
        : "=r"(a) : "l"(p));
    return a;
}
__device__ __forceinline__ uint32_t f16pair(float lo, float hi) {
    uint32_t r;
    asm("cvt.rn.f16x2.f32 %0, %1, %2;" : "=r"(r) : "f"(hi), "f"(lo));
    return r;
}
__device__ __forceinline__ unsigned short f16one(float v) {
    unsigned short r;
    asm("cvt.rn.f16.f32 %0, %1;" : "=h"(r) : "f"(v));
    return r;
}
__device__ __forceinline__ void ldsm4(uint32_t* r, uint32_t addr) {
    asm volatile("ldmatrix.sync.aligned.m8n8.x4.shared.b16 {%0,%1,%2,%3}, [%4];"
                 : "=r"(r[0]), "=r"(r[1]), "=r"(r[2]), "=r"(r[3]) : "r"(addr));
}
__device__ __forceinline__ void hmma(float* d, uint32_t a0, uint32_t a1,
                                     uint32_t a2, uint32_t a3,
                                     uint32_t b0, uint32_t b1) {
    asm volatile("mma.sync.aligned.m16n8k16.row.col.f32.f16.f16.f32 "
                 "{%0,%1,%2,%3}, {%4,%5,%6,%7}, {%8,%9}, {%0,%1,%2,%3};"
                 : "+f"(d[0]), "+f"(d[1]), "+f"(d[2]), "+f"(d[3])
                 : "r"(a0), "r"(a1), "r"(a2), "r"(a3), "r"(b0), "r"(b1));
}
#define CP_ASYNC16(dst, src) \
    asm volatile("cp.async.cg.shared.global [%0], [%1], 16;" \
                 :: "r"(dst), "l"(src) : "memory")
#define CP_COMMIT() asm volatile("cp.async.commit_group;" ::: "memory")
#define CP_WAIT1()  asm volatile("cp.async.wait_group 1;" ::: "memory")

// ---------------------------------------------------------------------------
// Conv weights: fold BN scale + convert to fp16 pairs [co][K/2] in one pass.
// ---------------------------------------------------------------------------
__global__ void wcvt_kernel(const float* __restrict__ conv_w,
                            const float* __restrict__ gamma,
                            const float* __restrict__ var) {
    int idx = blockIdx.x * blockDim.x + threadIdx.x;
    if (idx >= C_OUT * (KTOT / 2)) return;
    int co = idx >> 11;
    int c2 = idx & 2047;
    int kg = c2 * 2;                 // even k-index; k and k+1 share ci
    int ci = kg >> 4, k = kg & 15;
    float inv = gamma[co] * rsqrtf(var[co] + 1e-5f);
    const float* src = conv_w + ((size_t)co * C_IN + ci) * KW + k;
    g_wh[idx] = f16pair(src[0] * inv, src[1] * inv);
}

// ---------------------------------------------------------------------------
// prep: t<128 -> b12[j]; t in [128,192) -> folded conv bias g_cb.
// ---------------------------------------------------------------------------
__global__ void prep_kernel(const float* __restrict__ fc2_w,
                            const float* __restrict__ fc2_b,
                            const float* __restrict__ fc1_b,
                            const float* __restrict__ conv_b,
                            const float* __restrict__ gamma,
                            const float* __restrict__ beta,
                            const float* __restrict__ mean,
                            const float* __restrict__ var) {
    int t = threadIdx.x;
    if (t < H2) {
        float s = fc2_b[t];
        for (int h = 0; h < H1; h++) s = fmaf(fc2_w[t * H1 + h], fc1_b[h], s);
        g_b12[t] = s;
    } else if (t < H2 + C_OUT) {
        int co = t - H2;
        float inv = gamma[co] * rsqrtf(var[co] + 1e-5f);
        g_cb[co] = (conv_b[co] - mean[co]) * inv + beta[co];
    }
}

// ---------------------------------------------------------------------------
// fc1 transpose + cvt: [h=512][f=3904] fp32 -> g_f1h [f][h/2] fp16x2.
// grid (122, 8): tile 32 f x 64 h.
// ---------------------------------------------------------------------------
__global__ void __launch_bounds__(256) f1t_kernel(const float* __restrict__ fc1_w) {
    __shared__ float s[64][33];
    int t  = threadIdx.x;
    int f0 = blockIdx.x * 32;
    int h0 = blockIdx.y * 64;
#pragma unroll
    for (int it = 0; it < 8; it++) {
        int idx = it * 256 + t;
        int hh = idx >> 5, ff = idx & 31;
        s[hh][ff] = fc1_w[(size_t)(h0 + hh) * FLAT + f0 + ff];
    }
    __syncthreads();
    int hb2 = blockIdx.y * 32;
#pragma unroll
    for (int it = 0; it < 4; it++) {
        int idx = it * 256 + t;
        int ff = idx >> 5, pi = idx & 31;
        g_f1h[(size_t)(f0 + ff) * H12 + hb2 + pi] =
            f16pair(s[2 * pi][ff], s[2 * pi + 1][ff]);
    }
}

// ---------------------------------------------------------------------------
// fc2 cvt: [128][512] fp32 -> g_f2h [j][h/2] fp16x2. grid 128.
// ---------------------------------------------------------------------------
__global__ void f2cvt_kernel(const float* __restrict__ fc2_w) {
    int idx = blockIdx.x * 256 + threadIdx.x;
    if (idx >= H2 * H12) return;
    g_f2h[idx] = f16pair(fc2_w[2 * idx], fc2_w[2 * idx + 1]);
}

// ---------------------------------------------------------------------------
// W12 = fc2 @ fc1 via mma.sync. M=128 j, N=32 f per block (grid 122), K=512.
// Epilogue writes fp16 halves directly into permuted [j][l*64+co] layout.
// ---------------------------------------------------------------------------
__global__ void __launch_bounds__(256) w12mma_kernel() {
    __shared__ uint32_t asm_[H2 * 32];     // A: fc2 tile, 128 rows x 128B swizzled
    __shared__ uint32_t bsm_[32 * 32];     // B: fc1T tile, 32 rows x 128B swizzled

    int t = threadIdx.x, w = t >> 5, lane = t & 31;
    int mw = w;                            // warp -> j16 tile
    uint32_t as_addr = smem_u32(asm_);
    uint32_t bs_addr = smem_u32(bsm_);
    int f0 = blockIdx.x * 32;

    float acc[4][4];
#pragma unroll
    for (int nt = 0; nt < 4; nt++)
#pragma unroll
        for (int r = 0; r < 4; r++) acc[nt][r] = 0.f;

    // A ldmatrix addressing (feats pattern): x4 = m0-7/k0, m8-15/k0, m0-7/k8, m8-15/k8
    int sub = lane >> 3, r8 = lane & 7;
    int arow = mw * 16 + (sub & 1) * 8 + r8;
    uint32_t akb   = (uint32_t)((sub >> 1) * 16);
    uint32_t abase = as_addr + (uint32_t)(arow * 128);
    uint32_t aswz  = (uint32_t)(r8 << 4);

    // B ldmatrix addressing (feats pattern): 2 x ldsm4 for 32 f rows
    int btile = lane >> 3, brow = lane & 7;
    uint32_t bbase[2];
    uint32_t bkb  = (uint32_t)((btile & 1) * 16);
    uint32_t bswz = (uint32_t)(brow << 4);
#pragma unroll
    for (int p = 0; p < 2; p++) {
        int floc = (2 * p + (btile >> 1)) * 8 + brow;
        bbase[p] = bs_addr + (uint32_t)(floc * 128);
    }

    // staging indices
    int wj = t >> 1, wh = t & 1;          // A rows 0..127, halves
    char* arowp = (char*)asm_ + wj * 128;
    uint32_t awz = (uint32_t)((wj & 7) << 4);
    int am = t >> 3, akg = t & 7;         // B rows 0..31
    uint32_t bst = bs_addr + (uint32_t)(am * 128) +
                   (((uint32_t)(akg * 16)) ^ ((uint32_t)((am & 7) << 4)));

#pragma unroll 1
    for (int cc = 0; cc < 8; cc++) {       // K chunks of 64
        __syncthreads();
        {
            const uint4* src = (const uint4*)(g_f2h + (size_t)wj * H12 + cc * 32 + wh * 16);
#pragma unroll
            for (int qq = 0; qq < 4; qq++) {
                uint4 v = src[qq];
                *(uint4*)(arowp + (((uint32_t)(wh * 64 + qq * 16)) ^ awz)) = v;
            }
        }
        {
            uint4 v = *(const uint4*)(g_f1h + (size_t)(f0 + am) * H12 + cc * 32 + akg * 4);
            *(uint4*)((char*)bsm_ + (bst - bs_addr)) = v;
        }
        __syncthreads();

#pragma unroll
        for (int ks = 0; ks < 4; ks++) {
            uint32_t af[4];
            ldsm4(af, abase + (((uint32_t)(ks * 32) + akb) ^ aswz));
            uint32_t bf[8];
#pragma unroll
            for (int p = 0; p < 2; p++)
                ldsm4(&bf[4 * p], bbase[p] + (((uint32_t)(ks * 32) + bkb) ^ bswz));
#pragma unroll
            for (int nt = 0; nt < 4; nt++) {
                int bi = 4 * (nt >> 1) + 2 * (nt & 1);
                hmma(acc[nt], af[0], af[1], af[2], af[3], bf[bi], bf[bi + 1]);
            }
        }
    }

    // ---- epilogue: fp16 halves into permuted [j][l*64+co] layout ----
    unsigned short* dst = (unsigned short*)g_w12h;
    int r = lane >> 2, c = lane & 3;
#pragma unroll
    for (int nt = 0; nt < 4; nt++) {
#pragma unroll
        for (int e = 0; e < 4; e++) {
            int f = f0 + nt * 8 + 2 * c + (e & 1);
            int j = mw * 16 + r + (e >> 1) * 8;
            int co = f / L_OUT;
            int l  = f - co * L_OUT;
            dst[(size_t)j * FLAT + l * 64 + co] = f16one(acc[nt][e]);
        }
    }
}

// ---------------------------------------------------------------------------
// Conv + BN + ReLU via mma.sync, cp.async double-buffered pipeline.
// ---------------------------------------------------------------------------
#define XROWF 260
#define XBUF  2120
__global__ void __launch_bounds__(256) conv_mma_kernel(const float* __restrict__ x) {
    __shared__ float    xs[2][XBUF];
    __shared__ uint32_t bsm[2][C_OUT * 32];
    __shared__ float    cbs[C_OUT];

    int t = threadIdx.x, w = t >> 5, lane = t & 31;
    int q = w >> 2, quarter = w & 3;
    if (t < C_OUT) cbs[t] = g_cb[t];
    uint32_t xs_addr = smem_u32(xs);
    uint32_t bs_addr = smem_u32(bsm);

    int b = blockIdx.x * 2 + q;

    float acc[8][4];
#pragma unroll
    for (int nt = 0; nt < 8; nt++)
#pragma unroll
        for (int r = 0; r < 4; r++) acc[nt][r] = 0.f;

    int btile = lane >> 3, brow = lane & 7;
    uint32_t bbase[4], bkb[4], bsw[4];
#pragma unroll
    for (int p = 0; p < 4; p++) {
        int co = (2 * p + (btile >> 1)) * 8 + brow;
        bbase[p] = (uint32_t)(co * 128);
        bkb[p]   = (uint32_t)((btile & 1) * 16);
        bsw[p]   = (uint32_t)((co & 7) << 4);
    }

    int xci  = (t >> 6) & 3;
    int xoff = (t & 63) * 16;
    uint32_t xd0 = xs_addr + (uint32_t)(xci * (XROWF * 4)) + (uint32_t)xoff;
    uint32_t xd1 = xd0 + 4 * (XROWF * 4);
    const char* xsrc0 = (const char*)x + (size_t)(blockIdx.x * 2) * (C_IN * L_IN * 4)
                        + xci * 1024 + xoff;
    const char* xsrc1 = xsrc0 + (size_t)(C_IN * L_IN * 4);

    int brw = t >> 3;
    int bg  = t & 7;
    uint32_t bd0 = bs_addr + (uint32_t)(brw * 128) + (((uint32_t)(bg * 16)) ^ ((uint32_t)((brw & 7) << 4)));
    uint32_t bd1 = bs_addr + (uint32_t)((brw + 32) * 128) + (((uint32_t)(bg * 16)) ^ ((uint32_t)(((brw + 32) & 7) << 4)));
    const char* bsrc0 = (const char*)g_wh + (size_t)brw * 8192 + bg * 16;
    const char* bsrc1 = bsrc0 + (size_t)32 * 8192;

#define STAGE(cc, buf) do {                                                     \
    uint32_t xb = (uint32_t)((buf) * (XBUF * 4));                               \
    uint32_t bb = (uint32_t)((buf) * (C_OUT * 32 * 4));                         \
    size_t xo = (size_t)(cc) * 4096;                                            \
    size_t bo = (size_t)(cc) * 128;                                             \
    CP_ASYNC16(xd0 + xb, xsrc0 + xo);                                           \
    CP_ASYNC16(xd1 + xb, xsrc1 + xo);                                           \
    CP_ASYNC16(bd0 + bb, bsrc0 + bo);                                           \
    CP_ASYNC16(bd1 + bb, bsrc1 + bo);                                           \
} while (0)

    STAGE(0, 0);
    CP_COMMIT();

    int c = lane & 3, rq = lane >> 2;
    int lbase = quarter * 16;

#pragma unroll 1
    for (int cc = 0; cc < NCHUNK; cc++) {
        __syncthreads();
        if (cc < NCHUNK - 1) STAGE(cc + 1, (cc + 1) & 1);
        CP_COMMIT();
        CP_WAIT1();
        __syncthreads();

        int buf = cc & 1;
        uint32_t bbuf = bs_addr + (uint32_t)(buf * (C_OUT * 32 * 4));
        const float* xbuf = &xs[buf][q * 4 * XROWF];

#pragma unroll
        for (int ks = 0; ks < 4; ks++) {
            uint32_t bfr[16];
#pragma unroll
            for (int p = 0; p < 4; p++) {
                uint32_t addr = bbuf + bbase[p] + (((uint32_t)(ks * 32) + bkb[p]) ^ bsw[p]);
                ldsm4(&bfr[4 * p], addr);
            }
            const float2* xp = (const float2*)(xbuf + ks * XROWF);
            int e0 = 2 * (lbase + rq) + c;
            float2 v0 = xp[e0];
            float2 v1 = xp[e0 + 16];
            float2 v2 = xp[e0 + 4];
            float2 v3 = xp[e0 + 20];
            uint32_t a0 = f16pair(v0.x, v0.y);
            uint32_t a1 = f16pair(v1.x, v1.y);
            uint32_t a2 = f16pair(v2.x, v2.y);
            uint32_t a3 = f16pair(v3.x, v3.y);
#pragma unroll
            for (int nt = 0; nt < 8; nt++) {
                int bi = 4 * (nt >> 1) + 2 * (nt & 1);
                hmma(acc[nt], a0, a1, a2, a3, bfr[bi], bfr[bi + 1]);
            }
        }
    }

    unsigned* dst = g_acth + (size_t)b * FLAT2;
    int l1 = lbase + rq;
    int l2 = l1 + 8;
#pragma unroll
    for (int nt = 0; nt < 8; nt++) {
        int co0 = nt * 8 + 2 * c;
        float cb0 = cbs[co0], cb1 = cbs[co0 + 1];
        if (l1 < L_OUT) {
            float v0 = acc[nt][0] + cb0;
            float v1 = acc[nt][1] + cb1;
            dst[l1 * 32 + nt * 4 + c] = f16pair(v0 > 0.f ? v0 : 0.f, v1 > 0.f ? v1 : 0.f);
        }
        if (l2 < L_OUT) {
            float v2 = acc[nt][2] + cb0;
            float v3 = acc[nt][3] + cb1;
            dst[l2 * 32 + nt * 4 + c] = f16pair(v2 > 0.f ? v2 : 0.f, v3 > 0.f ? v3 : 0.f);
        }
    }
#undef STAGE
}

// ---------------------------------------------------------------------------
// feats = act @ W12^T + b12 via mma.sync, fused parabit heads -> out.
// ---------------------------------------------------------------------------
__global__ void __launch_bounds__(256) feats_mma_kernel(const float* __restrict__ bit_w,
                                                        const float* __restrict__ bit_b,
                                                        float* __restrict__ out) {
    __shared__ uint32_t as_[32 * 32];
    __shared__ uint32_t ws_[H2 * 32];
    __shared__ float sb12[H2], sbw[H2 * 2], sbb[H2 * 2];

    int t = threadIdx.x, w = t >> 5, lane = t & 31;
    int mw = w >> 2, jw = w & 3;
    if (t < H2) sb12[t] = g_b12[t];
    if (t < H2 * 2) { sbw[t] = bit_w[t]; sbb[t] = bit_b[t]; }
    uint32_t as_addr = smem_u32(as_);
    uint32_t ws_addr = smem_u32(ws_);

    int b0 = blockIdx.x * 32;

    float acc[4][4];
#pragma unroll
    for (int nt = 0; nt < 4; nt++)
#pragma unroll
        for (int r = 0; r < 4; r++) acc[nt][r] = 0.f;

    int sub = lane >> 3, r8 = lane & 7;
    int arow = mw * 16 + (sub & 1) * 8 + r8;
    uint32_t akb  = (uint32_t)((sub >> 1) * 16);
    uint32_t abase = as_addr + (uint32_t)(arow * 128);
    uint32_t aswz = (uint32_t)(r8 << 4);

    int btile = lane >> 3, brow = lane & 7;
    uint32_t bbase[2];
    uint32_t bkb = (uint32_t)((btile & 1) * 16);
    uint32_t bswz = (uint32_t)(brow << 4);
#pragma unroll
    for (int p = 0; p < 2; p++) {
        int jloc = (2 * p + (btile >> 1)) * 8 + brow;
        bbase[p] = ws_addr + (uint32_t)((jw * 32 + jloc) * 128);
    }

    int am  = t >> 3;
    int akg = t & 7;
    uint32_t ast = as_addr + (uint32_t)(am * 128) + (((uint32_t)(akg * 16)) ^ ((uint32_t)((am & 7) << 4)));
    int wj  = t >> 1;
    int wh  = t & 1;
    char* wrow = (char*)ws_ + wj * 128;
    uint32_t wswz = (uint32_t)((wj & 7) << 4);

#pragma unroll 1
    for (int cc = 0; cc < 61; cc++) {
        __syncthreads();
        {
            uint4 v = *(const uint4*)(g_acth + (size_t)(b0 + am) * FLAT2 + cc * 32 + akg * 4);
            *(uint4*)((char*)as_ + (ast - as_addr)) = v;
        }
        {
            const uint4* src = (const uint4*)(g_w12h + (size_t)wj * FLAT2 + cc * 32 + wh * 16);
#pragma unroll
            for (int qq = 0; qq < 4; qq++) {
                uint4 v = src[qq];
                *(uint4*)(wrow + (((uint32_t)(wh * 64 + qq * 16)) ^ wswz)) = v;
            }
        }
        __syncthreads();

#pragma unroll
        for (int ks = 0; ks < 4; ks++) {
            uint32_t af[4];
            ldsm4(af, abase + (((uint32_t)(ks * 32) + akb) ^ aswz));
            uint32_t bf[8];
#pragma unroll
            for (int p = 0; p < 2; p++)
                ldsm4(&bf[4 * p], bbase[p] + (((uint32_t)(ks * 32) + bkb) ^ bswz));
#pragma unroll
            for (int nt = 0; nt < 4; nt++) {
                int bi = 4 * (nt >> 1) + 2 * (nt & 1);
                hmma(acc[nt], af[0], af[1], af[2], af[3], bf[bi], bf[bi + 1]);
            }
        }
    }

    int r = lane >> 2, c = lane & 3;
#pragma unroll
    for (int nt = 0; nt < 4; nt++) {
        int j0 = jw * 32 + nt * 8 + 2 * c;
        float bj0 = sb12[j0], bj1 = sb12[j0 + 1];
        float bw00 = sbw[j0 * 2], bw01 = sbw[j0 * 2 + 1];
        float bw10 = sbw[j0 * 2 + 2], bw11 = sbw[j0 * 2 + 3];
        float bb00 = sbb[j0 * 2], bb01 = sbb[j0 * 2 + 1];
        float bb10 = sbb[j0 * 2 + 2], bb11 = sbb[j0 * 2 + 3];
        {
            int b = b0 + mw * 16 + r;
            float f0 = acc[nt][0] + bj0;
            float f1 = acc[nt][1] + bj1;
            float4 o = make_float4(fmaf(f0, bw00, bb00), fmaf(f0, bw01, bb01),
                                   fmaf(f1, bw10, bb10), fmaf(f1, bw11, bb11));
            *(float4*)(out + ((size_t)b * H2 + j0) * 2) = o;
        }
        {
            int b = b0 + mw * 16 + r + 8;
            float f2 = acc[nt][2] + bj0;
            float f3 = acc[nt][3] + bj1;
            float4 o = make_float4(fmaf(f2, bw00, bb00), fmaf(f2, bw01, bb01),
                                   fmaf(f3, bw10, bb10), fmaf(f3, bw11, bb11));
            *(float4*)(out + ((size_t)b * H2 + j0) * 2) = o;
        }
    }
}

// ---------------------------------------------------------------------------
extern "C" void kernel_launch(void* const* d_in, const int* in_sizes, int n_in,
                              void* d_out, int out_size) {
    const float* x      = (const float*)d_in[0];
    const float* conv_w = (const float*)d_in[1];
    const float* conv_b = (const float*)d_in[2];
    const float* gamma  = (const float*)d_in[3];
    const float* beta   = (const float*)d_in[4];
    const float* mean   = (const float*)d_in[5];
    const float* var    = (const float*)d_in[6];
    const float* fc1_w  = (const float*)d_in[7];
    const float* fc1_b  = (const float*)d_in[8];
    const float* fc2_w  = (const float*)d_in[9];
    const float* fc2_b  = (const float*)d_in[10];
    const float* bit_w  = (const float*)d_in[11];
    const float* bit_b  = (const float*)d_in[12];
    float* out = (float*)d_out;

    wcvt_kernel<<<(C_OUT * (KTOT / 2) + 255) / 256, 256>>>(conv_w, gamma, var);
    prep_kernel<<<1, 256>>>(fc2_w, fc2_b, fc1_b, conv_b, gamma, beta, mean, var);
    f1t_kernel<<<dim3(FLAT / 32, 8), 256>>>(fc1_w);
    f2cvt_kernel<<<(H2 * H12 + 255) / 256, 256>>>(fc2_w);
    w12mma_kernel<<<FLAT / 32, 256>>>();
    conv_mma_kernel<<<BB / 2, 256>>>(x);
    feats_mma_kernel<<<BB / 32, 256>>>(bit_w, bit_b, out);
}

// round 10
// speedup vs baseline: 8.3483x; 1.0599x over previous
#include <cuda_runtime.h>
#include <cstdint>

#define BB 2048
#define C_IN 256
#define L_IN 256
#define C_OUT 64
#define KW 16
#define L_OUT 61
#define FLAT 3904    // 64*61
#define FLAT2 1952   // FLAT/2 (f16x2 pairs)
#define H1 512
#define H12 256      // H1/2 pairs
#define H2 128
#define KTOT 4096    // C_IN*KW
#define NCHUNK 64    // conv K chunks of 64 (4 ci each)

// ---------------- scratch (static device arrays; no allocation) -------------
__device__ unsigned g_acth[(size_t)BB * FLAT2];   // act fp16x2, [b][(l*64+co)/2]
__device__ unsigned g_w12h[H2 * FLAT2];           // W12 fp16x2, [j][(l*64+co)/2]
__device__ float    g_b12[H2];
__device__ float    g_cb[C_OUT];
__device__ unsigned g_wh[C_OUT * (KTOT / 2)];     // conv weights fp16x2, [co][K/2]
__device__ unsigned g_f1h[(size_t)FLAT * H12];    // fc1^T fp16x2, [f][h/2]
__device__ unsigned g_f2h[H2 * H12];              // fc2 fp16x2, [j][h/2]

// ---------------- PTX helpers ----------------------------------------------
__device__ __forceinline__ uint32_t smem_u32(const void* p) {
    uint32_t a;
    asm("{ .reg .u64 t; cvta.to.shared.u64 t, %1; cvt.u32.u64 %0, t; }"
        : "=r"(a) : "l"(p));
    return a;
}
__device__ __forceinline__ uint32_t f16pair(float lo, float hi) {
    uint32_t r;
    asm("cvt.rn.f16x2.f32 %0, %1, %2;" : "=r"(r) : "f"(hi), "f"(lo));
    return r;
}
__device__ __forceinline__ unsigned short f16one(float v) {
    unsigned short r;
    asm("cvt.rn.f16.f32 %0, %1;" : "=h"(r) : "f"(v));
    return r;
}
__device__ __forceinline__ void ldsm4(uint32_t* r, uint32_t addr) {
    asm volatile("ldmatrix.sync.aligned.m8n8.x4.shared.b16 {%0,%1,%2,%3}, [%4];"
                 : "=r"(r[0]), "=r"(r[1]), "=r"(r[2]), "=r"(r[3]) : "r"(addr));
}
__device__ __forceinline__ void hmma(float* d, uint32_t a0, uint32_t a1,
                                     uint32_t a2, uint32_t a3,
                                     uint32_t b0, uint32_t b1) {
    asm volatile("mma.sync.aligned.m16n8k16.row.col.f32.f16.f16.f32 "
                 "{%0,%1,%2,%3}, {%4,%5,%6,%7}, {%8,%9}, {%0,%1,%2,%3};"
                 : "+f"(d[0]), "+f"(d[1]), "+f"(d[2]), "+f"(d[3])
                 : "r"(a0), "r"(a1), "r"(a2), "r"(a3), "r"(b0), "r"(b1));
}
#define CP_ASYNC16(dst, src) \
    asm volatile("cp.async.cg.shared.global [%0], [%1], 16;" \
                 :: "r"(dst), "l"(src) : "memory")
#define CP_COMMIT() asm volatile("cp.async.commit_group;" ::: "memory")
#define CP_WAIT1()  asm volatile("cp.async.wait_group 1;" ::: "memory")

// ---------------------------------------------------------------------------
// prep_all: one launch for all weight preprocessing.
//   blocks [0,512)   : conv weight fold+cvt  (g_wh)
//   blocks [512,640) : fc2 cvt               (g_f2h)
//   block  640       : b12 + folded conv bias
// ---------------------------------------------------------------------------
__global__ void __launch_bounds__(256) prep_all_kernel(
        const float* __restrict__ conv_w, const float* __restrict__ conv_b,
        const float* __restrict__ gamma,  const float* __restrict__ beta,
        const float* __restrict__ mean,   const float* __restrict__ var,
        const float* __restrict__ fc1_b,  const float* __restrict__ fc2_w,
        const float* __restrict__ fc2_b) {
    int bid = blockIdx.x, t = threadIdx.x;
    if (bid < 512) {
        int idx = bid * 256 + t;              // exactly C_OUT*(KTOT/2)
        int co = idx >> 11;
        int kg = (idx & 2047) * 2;
        int ci = kg >> 4, k = kg & 15;
        float inv = gamma[co] * rsqrtf(var[co] + 1e-5f);
        const float* src = conv_w + ((size_t)co * C_IN + ci) * KW + k;
        g_wh[idx] = f16pair(src[0] * inv, src[1] * inv);
    } else if (bid < 640) {
        int idx = (bid - 512) * 256 + t;      // exactly H2*H12
        g_f2h[idx] = f16pair(fc2_w[2 * idx], fc2_w[2 * idx + 1]);
    } else {
        if (t < H2) {
            float s = fc2_b[t];
            for (int h = 0; h < H1; h++) s = fmaf(fc2_w[t * H1 + h], fc1_b[h], s);
            g_b12[t] = s;
        } else if (t < H2 + C_OUT) {
            int co = t - H2;
            float inv = gamma[co] * rsqrtf(var[co] + 1e-5f);
            g_cb[co] = (conv_b[co] - mean[co]) * inv + beta[co];
        }
    }
}

// ---------------------------------------------------------------------------
// fc1 transpose + cvt: [h=512][f=3904] fp32 -> g_f1h [f][h/2] fp16x2.
// ---------------------------------------------------------------------------
__global__ void __launch_bounds__(256) f1t_kernel(const float* __restrict__ fc1_w) {
    __shared__ float s[64][33];
    int t  = threadIdx.x;
    int f0 = blockIdx.x * 32;
    int h0 = blockIdx.y * 64;
#pragma unroll
    for (int it = 0; it < 8; it++) {
        int idx = it * 256 + t;
        int hh = idx >> 5, ff = idx & 31;
        s[hh][ff] = fc1_w[(size_t)(h0 + hh) * FLAT + f0 + ff];
    }
    __syncthreads();
    int hb2 = blockIdx.y * 32;
#pragma unroll
    for (int it = 0; it < 4; it++) {
        int idx = it * 256 + t;
        int ff = idx >> 5, pi = idx & 31;
        g_f1h[(size_t)(f0 + ff) * H12 + hb2 + pi] =
            f16pair(s[2 * pi][ff], s[2 * pi + 1][ff]);
    }
}

// ---------------------------------------------------------------------------
// W12 = fc2 @ fc1 via mma.sync. M=128 j, N=32 f per block (grid 122), K=512.
// ---------------------------------------------------------------------------
__global__ void __launch_bounds__(256) w12mma_kernel() {
    __shared__ uint32_t asm_[H2 * 32];
    __shared__ uint32_t bsm_[32 * 32];

    int t = threadIdx.x, w = t >> 5, lane = t & 31;
    int mw = w;
    uint32_t as_addr = smem_u32(asm_);
    uint32_t bs_addr = smem_u32(bsm_);
    int f0 = blockIdx.x * 32;

    float acc[4][4];
#pragma unroll
    for (int nt = 0; nt < 4; nt++)
#pragma unroll
        for (int r = 0; r < 4; r++) acc[nt][r] = 0.f;

    int sub = lane >> 3, r8 = lane & 7;
    int arow = mw * 16 + (sub & 1) * 8 + r8;
    uint32_t akb   = (uint32_t)((sub >> 1) * 16);
    uint32_t abase = as_addr + (uint32_t)(arow * 128);
    uint32_t aswz  = (uint32_t)(r8 << 4);

    int btile = lane >> 3, brow = lane & 7;
    uint32_t bbase[2];
    uint32_t bkb  = (uint32_t)((btile & 1) * 16);
    uint32_t bswz = (uint32_t)(brow << 4);
#pragma unroll
    for (int p = 0; p < 2; p++) {
        int floc = (2 * p + (btile >> 1)) * 8 + brow;
        bbase[p] = bs_addr + (uint32_t)(floc * 128);
    }

    int wj = t >> 1, wh = t & 1;
    char* arowp = (char*)asm_ + wj * 128;
    uint32_t awz = (uint32_t)((wj & 7) << 4);
    int am = t >> 3, akg = t & 7;
    uint32_t bst = bs_addr + (uint32_t)(am * 128) +
                   (((uint32_t)(akg * 16)) ^ ((uint32_t)((am & 7) << 4)));

#pragma unroll 1
    for (int cc = 0; cc < 8; cc++) {
        __syncthreads();
        {
            const uint4* src = (const uint4*)(g_f2h + (size_t)wj * H12 + cc * 32 + wh * 16);
#pragma unroll
            for (int qq = 0; qq < 4; qq++) {
                uint4 v = src[qq];
                *(uint4*)(arowp + (((uint32_t)(wh * 64 + qq * 16)) ^ awz)) = v;
            }
        }
        {
            uint4 v = *(const uint4*)(g_f1h + (size_t)(f0 + am) * H12 + cc * 32 + akg * 4);
            *(uint4*)((char*)bsm_ + (bst - bs_addr)) = v;
        }
        __syncthreads();

#pragma unroll
        for (int ks = 0; ks < 4; ks++) {
            uint32_t af[4];
            ldsm4(af, abase + (((uint32_t)(ks * 32) + akb) ^ aswz));
            uint32_t bf[8];
#pragma unroll
            for (int p = 0; p < 2; p++)
                ldsm4(&bf[4 * p], bbase[p] + (((uint32_t)(ks * 32) + bkb) ^ bswz));
#pragma unroll
            for (int nt = 0; nt < 4; nt++) {
                int bi = 4 * (nt >> 1) + 2 * (nt & 1);
                hmma(acc[nt], af[0], af[1], af[2], af[3], bf[bi], bf[bi + 1]);
            }
        }
    }

    unsigned short* dst = (unsigned short*)g_w12h;
    int r = lane >> 2, c = lane & 3;
#pragma unroll
    for (int nt = 0; nt < 4; nt++) {
#pragma unroll
        for (int e = 0; e < 4; e++) {
            int f = f0 + nt * 8 + 2 * c + (e & 1);
            int j = mw * 16 + r + (e >> 1) * 8;
            int co = f / L_OUT;
            int l  = f - co * L_OUT;
            dst[(size_t)j * FLAT + l * 64 + co] = f16one(acc[nt][e]);
        }
    }
}

// ---------------------------------------------------------------------------
// Conv + BN + ReLU via mma.sync, cp.async double-buffered pipeline. (unchanged)
// ---------------------------------------------------------------------------
#define XROWF 260
#define XBUF  2120
__global__ void __launch_bounds__(256) conv_mma_kernel(const float* __restrict__ x) {
    __shared__ float    xs[2][XBUF];
    __shared__ uint32_t bsm[2][C_OUT * 32];
    __shared__ float    cbs[C_OUT];

    int t = threadIdx.x, w = t >> 5, lane = t & 31;
    int q = w >> 2, quarter = w & 3;
    if (t < C_OUT) cbs[t] = g_cb[t];
    uint32_t xs_addr = smem_u32(xs);
    uint32_t bs_addr = smem_u32(bsm);

    int b = blockIdx.x * 2 + q;

    float acc[8][4];
#pragma unroll
    for (int nt = 0; nt < 8; nt++)
#pragma unroll
        for (int r = 0; r < 4; r++) acc[nt][r] = 0.f;

    int btile = lane >> 3, brow = lane & 7;
    uint32_t bbase[4], bkb[4], bsw[4];
#pragma unroll
    for (int p = 0; p < 4; p++) {
        int co = (2 * p + (btile >> 1)) * 8 + brow;
        bbase[p] = (uint32_t)(co * 128);
        bkb[p]   = (uint32_t)((btile & 1) * 16);
        bsw[p]   = (uint32_t)((co & 7) << 4);
    }

    int xci  = (t >> 6) & 3;
    int xoff = (t & 63) * 16;
    uint32_t xd0 = xs_addr + (uint32_t)(xci * (XROWF * 4)) + (uint32_t)xoff;
    uint32_t xd1 = xd0 + 4 * (XROWF * 4);
    const char* xsrc0 = (const char*)x + (size_t)(blockIdx.x * 2) * (C_IN * L_IN * 4)
                        + xci * 1024 + xoff;
    const char* xsrc1 = xsrc0 + (size_t)(C_IN * L_IN * 4);

    int brw = t >> 3;
    int bg  = t & 7;
    uint32_t bd0 = bs_addr + (uint32_t)(brw * 128) + (((uint32_t)(bg * 16)) ^ ((uint32_t)((brw & 7) << 4)));
    uint32_t bd1 = bs_addr + (uint32_t)((brw + 32) * 128) + (((uint32_t)(bg * 16)) ^ ((uint32_t)(((brw + 32) & 7) << 4)));
    const char* bsrc0 = (const char*)g_wh + (size_t)brw * 8192 + bg * 16;
    const char* bsrc1 = bsrc0 + (size_t)32 * 8192;

#define STAGE(cc, buf) do {                                                     \
    uint32_t xb = (uint32_t)((buf) * (XBUF * 4));                               \
    uint32_t bb = (uint32_t)((buf) * (C_OUT * 32 * 4));                         \
    size_t xo = (size_t)(cc) * 4096;                                            \
    size_t bo = (size_t)(cc) * 128;                                             \
    CP_ASYNC16(xd0 + xb, xsrc0 + xo);                                           \
    CP_ASYNC16(xd1 + xb, xsrc1 + xo);                                           \
    CP_ASYNC16(bd0 + bb, bsrc0 + bo);                                           \
    CP_ASYNC16(bd1 + bb, bsrc1 + bo);                                           \
} while (0)

    STAGE(0, 0);
    CP_COMMIT();

    int c = lane & 3, rq = lane >> 2;
    int lbase = quarter * 16;

#pragma unroll 1
    for (int cc = 0; cc < NCHUNK; cc++) {
        __syncthreads();
        if (cc < NCHUNK - 1) STAGE(cc + 1, (cc + 1) & 1);
        CP_COMMIT();
        CP_WAIT1();
        __syncthreads();

        int buf = cc & 1;
        uint32_t bbuf = bs_addr + (uint32_t)(buf * (C_OUT * 32 * 4));
        const float* xbuf = &xs[buf][q * 4 * XROWF];

#pragma unroll
        for (int ks = 0; ks < 4; ks++) {
            uint32_t bfr[16];
#pragma unroll
            for (int p = 0; p < 4; p++) {
                uint32_t addr = bbuf + bbase[p] + (((uint32_t)(ks * 32) + bkb[p]) ^ bsw[p]);
                ldsm4(&bfr[4 * p], addr);
            }
            const float2* xp = (const float2*)(xbuf + ks * XROWF);
            int e0 = 2 * (lbase + rq) + c;
            float2 v0 = xp[e0];
            float2 v1 = xp[e0 + 16];
            float2 v2 = xp[e0 + 4];
            float2 v3 = xp[e0 + 20];
            uint32_t a0 = f16pair(v0.x, v0.y);
            uint32_t a1 = f16pair(v1.x, v1.y);
            uint32_t a2 = f16pair(v2.x, v2.y);
            uint32_t a3 = f16pair(v3.x, v3.y);
#pragma unroll
            for (int nt = 0; nt < 8; nt++) {
                int bi = 4 * (nt >> 1) + 2 * (nt & 1);
                hmma(acc[nt], a0, a1, a2, a3, bfr[bi], bfr[bi + 1]);
            }
        }
    }

    unsigned* dst = g_acth + (size_t)b * FLAT2;
    int l1 = lbase + rq;
    int l2 = l1 + 8;
#pragma unroll
    for (int nt = 0; nt < 8; nt++) {
        int co0 = nt * 8 + 2 * c;
        float cb0 = cbs[co0], cb1 = cbs[co0 + 1];
        if (l1 < L_OUT) {
            float v0 = acc[nt][0] + cb0;
            float v1 = acc[nt][1] + cb1;
            dst[l1 * 32 + nt * 4 + c] = f16pair(v0 > 0.f ? v0 : 0.f, v1 > 0.f ? v1 : 0.f);
        }
        if (l2 < L_OUT) {
            float v2 = acc[nt][2] + cb0;
            float v3 = acc[nt][3] + cb1;
            dst[l2 * 32 + nt * 4 + c] = f16pair(v2 > 0.f ? v2 : 0.f, v3 > 0.f ? v3 : 0.f);
        }
    }
#undef STAGE
}

// ---------------------------------------------------------------------------
// feats = act @ W12^T + b12 via mma.sync, fused parabit heads -> out.
// M=16 batches per block (grid 128). Warp w -> j-slice [w*16, w*16+16).
// ---------------------------------------------------------------------------
__global__ void __launch_bounds__(256) feats_mma_kernel(const float* __restrict__ bit_w,
                                                        const float* __restrict__ bit_b,
                                                        float* __restrict__ out) {
    __shared__ uint32_t as_[16 * 32];     // A tile: 16 rows x 128B, swizzled
    __shared__ uint32_t ws_[H2 * 32];     // B tile: 128 rows x 128B, swizzled
    __shared__ float sb12[H2], sbw[H2 * 2], sbb[H2 * 2];

    int t = threadIdx.x, w = t >> 5, lane = t & 31;
    if (t < H2) sb12[t] = g_b12[t];
    if (t < H2 * 2) { sbw[t] = bit_w[t]; sbb[t] = bit_b[t]; }
    uint32_t as_addr = smem_u32(as_);
    uint32_t ws_addr = smem_u32(ws_);

    int b0 = blockIdx.x * 16;

    float acc[2][4];
#pragma unroll
    for (int nt = 0; nt < 2; nt++)
#pragma unroll
        for (int r = 0; r < 4; r++) acc[nt][r] = 0.f;

    // A frag addressing: x4 = (m0-7,k0),(m8-15,k0),(m0-7,k8),(m8-15,k8)
    int sub = lane >> 3, r8 = lane & 7;
    int arow = (sub & 1) * 8 + r8;
    uint32_t akb   = (uint32_t)((sub >> 1) * 16);
    uint32_t abase = as_addr + (uint32_t)(arow * 128);
    uint32_t aswz  = (uint32_t)(r8 << 4);

    // B frag addressing: one ldsm4 covers j16 x k16 for this warp:
    // group g: (j-tile g>>1, k-half g&1)
    int g = lane >> 3, brow = lane & 7;
    int bj  = w * 16 + (g >> 1) * 8 + brow;
    uint32_t bkb  = (uint32_t)((g & 1) * 16);
    uint32_t bbase = ws_addr + (uint32_t)(bj * 128);
    uint32_t bswz = (uint32_t)(brow << 4);

    // staging: A rows by threads t<128; B rows by all threads
    int am = t >> 3, akg = t & 7;          // am 0..31, only am<16 valid
    uint32_t ast = as_addr + (uint32_t)(am * 128) +
                   (((uint32_t)(akg * 16)) ^ ((uint32_t)((am & 7) << 4)));
    int wj = t >> 1, wh = t & 1;
    char* wrow = (char*)ws_ + wj * 128;
    uint32_t wswz = (uint32_t)((wj & 7) << 4);

#pragma unroll 1
    for (int cc = 0; cc < 61; cc++) {
        __syncthreads();
        if (am < 16) {
            uint4 v = *(const uint4*)(g_acth + (size_t)(b0 + am) * FLAT2 + cc * 32 + akg * 4);
            *(uint4*)((char*)as_ + (ast - as_addr)) = v;
        }
        {
            const uint4* src = (const uint4*)(g_w12h + (size_t)wj * FLAT2 + cc * 32 + wh * 16);
#pragma unroll
            for (int qq = 0; qq < 4; qq++) {
                uint4 v = src[qq];
                *(uint4*)(wrow + (((uint32_t)(wh * 64 + qq * 16)) ^ wswz)) = v;
            }
        }
        __syncthreads();

#pragma unroll
        for (int ks = 0; ks < 4; ks++) {
            uint32_t af[4];
            ldsm4(af, abase + (((uint32_t)(ks * 32) + akb) ^ aswz));
            uint32_t bf[4];
            ldsm4(bf, bbase + (((uint32_t)(ks * 32) + bkb) ^ bswz));
#pragma unroll
            for (int nt = 0; nt < 2; nt++)
                hmma(acc[nt], af[0], af[1], af[2], af[3], bf[2 * nt], bf[2 * nt + 1]);
        }
    }

    // ---- epilogue: + b12, parabit heads, write out ----
    int r = lane >> 2, c = lane & 3;
#pragma unroll
    for (int nt = 0; nt < 2; nt++) {
        int j0 = w * 16 + nt * 8 + 2 * c;
        float bj0 = sb12[j0], bj1 = sb12[j0 + 1];
        float bw00 = sbw[j0 * 2], bw01 = sbw[j0 * 2 + 1];
        float bw10 = sbw[j0 * 2 + 2], bw11 = sbw[j0 * 2 + 3];
        float bb00 = sbb[j0 * 2], bb01 = sbb[j0 * 2 + 1];
        float bb10 = sbb[j0 * 2 + 2], bb11 = sbb[j0 * 2 + 3];
        {
            int b = b0 + r;
            float f0 = acc[nt][0] + bj0;
            float f1 = acc[nt][1] + bj1;
            float4 o = make_float4(fmaf(f0, bw00, bb00), fmaf(f0, bw01, bb01),
                                   fmaf(f1, bw10, bb10), fmaf(f1, bw11, bb11));
            *(float4*)(out + ((size_t)b * H2 + j0) * 2) = o;
        }
        {
            int b = b0 + r + 8;
            float f2 = acc[nt][2] + bj0;
            float f3 = acc[nt][3] + bj1;
            float4 o = make_float4(fmaf(f2, bw00, bb00), fmaf(f2, bw01, bb01),
                                   fmaf(f3, bw10, bb10), fmaf(f3, bw11, bb11));
            *(float4*)(out + ((size_t)b * H2 + j0) * 2) = o;
        }
    }
}

// ---------------------------------------------------------------------------
extern "C" void kernel_launch(void* const* d_in, const int* in_sizes, int n_in,
                              void* d_out, int out_size) {
    const float* x      = (const float*)d_in[0];
    const float* conv_w = (const float*)d_in[1];
    const float* conv_b = (const float*)d_in[2];
    const float* gamma  = (const float*)d_in[3];
    const float* beta   = (const float*)d_in[4];
    const float* mean   = (const float*)d_in[5];
    const float* var    = (const float*)d_in[6];
    const float* fc1_w  = (const float*)d_in[7];
    const float* fc1_b  = (const float*)d_in[8];
    const float* fc2_w  = (const float*)d_in[9];
    const float* fc2_b  = (const float*)d_in[10];
    const float* bit_w  = (const float*)d_in[11];
    const float* bit_b  = (const float*)d_in[12];
    float* out = (float*)d_out;

    // One-time stream/event setup (first call is the uncaptured correctness
    // run; the capture call reuses these handles — no device allocations).
    static cudaStream_t s2 = nullptr;
    static cudaEvent_t evFork = nullptr, evJoin = nullptr;
    if (!s2) {
        cudaStreamCreateWithFlags(&s2, cudaStreamNonBlocking);
        cudaEventCreateWithFlags(&evFork, cudaEventDisableTiming);
        cudaEventCreateWithFlags(&evJoin, cudaEventDisableTiming);
    }

    // main stream: prep_all -> conv  |  s2: f1t -> w12mma (parallel to conv)
    prep_all_kernel<<<641, 256>>>(conv_w, conv_b, gamma, beta, mean, var,
                                  fc1_b, fc2_w, fc2_b);
    cudaEventRecord(evFork, 0);
    cudaStreamWaitEvent(s2, evFork, 0);
    f1t_kernel<<<dim3(FLAT / 32, 8), 256, 0, s2>>>(fc1_w);
    w12mma_kernel<<<FLAT / 32, 256, 0, s2>>>();
    cudaEventRecord(evJoin, s2);

    conv_mma_kernel<<<BB / 2, 256>>>(x);
    cudaStreamWaitEvent((cudaStream_t)0, evJoin, 0);
    feats_mma_kernel<<<BB / 16, 256>>>(bit_w, bit_b, out);
}

// round 11
// speedup vs baseline: 9.2515x; 1.1082x over previous
#include <cuda_runtime.h>
#include <cstdint>

#define BB 2048
#define C_IN 256
#define L_IN 256
#define C_OUT 64
#define KW 16
#define L_OUT 61
#define FLAT 3904    // 64*61
#define FLAT2 1952   // FLAT/2 (f16x2 pairs)
#define H1 512
#define H12 256      // H1/2 pairs
#define H2 128
#define KTOT 4096    // C_IN*KW
#define NCHUNK 64    // conv K chunks of 64 (4 ci each)

// ---------------- scratch (static device arrays; no allocation) -------------
__device__ unsigned g_acth[(size_t)BB * FLAT2];   // act fp16x2, [b][(l*64+co)/2]
__device__ unsigned g_w12h[H2 * FLAT2];           // W12 fp16x2, [j][(l*64+co)/2]
__device__ float    g_b12[H2];
__device__ float    g_cb[C_OUT];
__device__ unsigned g_wh[C_OUT * (KTOT / 2)];     // conv weights fp16x2, [co][K/2]
__device__ unsigned g_f1h[(size_t)FLAT * H12];    // fc1^T fp16x2, [f][h/2]
__device__ unsigned g_f2h[H2 * H12];              // fc2 fp16x2, [j][h/2]

// ---------------- PTX helpers ----------------------------------------------
__device__ __forceinline__ uint32_t smem_u32(const void* p) {
    uint32_t a;
    asm("{ .reg .u64 t; cvta.to.shared.u64 t, %1; cvt.u32.u64 %0, t; }"
        : "=r"(a) : "l"(p));
    return a;
}
__device__ __forceinline__ uint32_t f16pair(float lo, float hi) {
    uint32_t r;
    asm("cvt.rn.f16x2.f32 %0, %1, %2;" : "=r"(r) : "f"(hi), "f"(lo));
    return r;
}
__device__ __forceinline__ unsigned short f16one(float v) {
    unsigned short r;
    asm("cvt.rn.f16.f32 %0, %1;" : "=h"(r) : "f"(v));
    return r;
}
__device__ __forceinline__ void ldsm4(uint32_t* r, uint32_t addr) {
    asm volatile("ldmatrix.sync.aligned.m8n8.x4.shared.b16 {%0,%1,%2,%3}, [%4];"
                 : "=r"(r[0]), "=r"(r[1]), "=r"(r[2]), "=r"(r[3]) : "r"(addr));
}
__device__ __forceinline__ void hmma(float* d, uint32_t a0, uint32_t a1,
                                     uint32_t a2, uint32_t a3,
                                     uint32_t b0, uint32_t b1) {
    asm volatile("mma.sync.aligned.m16n8k16.row.col.f32.f16.f16.f32 "
                 "{%0,%1,%2,%3}, {%4,%5,%6,%7}, {%8,%9}, {%0,%1,%2,%3};"
                 : "+f"(d[0]), "+f"(d[1]), "+f"(d[2]), "+f"(d[3])
                 : "r"(a0), "r"(a1), "r"(a2), "r"(a3), "r"(b0), "r"(b1));
}
#define CP_ASYNC16(dst, src) \
    asm volatile("cp.async.cg.shared.global [%0], [%1], 16;" \
                 :: "r"(dst), "l"(src) : "memory")
#define CP_COMMIT() asm volatile("cp.async.commit_group;" ::: "memory")
#define CP_WAIT1()  asm volatile("cp.async.wait_group 1;" ::: "memory")

// ---------------------------------------------------------------------------
// prep_all: one launch for all weight preprocessing.
// ---------------------------------------------------------------------------
__global__ void __launch_bounds__(256) prep_all_kernel(
        const float* __restrict__ conv_w, const float* __restrict__ conv_b,
        const float* __restrict__ gamma,  const float* __restrict__ beta,
        const float* __restrict__ mean,   const float* __restrict__ var,
        const float* __restrict__ fc1_b,  const float* __restrict__ fc2_w,
        const float* __restrict__ fc2_b) {
    int bid = blockIdx.x, t = threadIdx.x;
    if (bid < 512) {
        int idx = bid * 256 + t;              // exactly C_OUT*(KTOT/2)
        int co = idx >> 11;
        int kg = (idx & 2047) * 2;
        int ci = kg >> 4, k = kg & 15;
        float inv = gamma[co] * rsqrtf(var[co] + 1e-5f);
        const float* src = conv_w + ((size_t)co * C_IN + ci) * KW + k;
        g_wh[idx] = f16pair(src[0] * inv, src[1] * inv);
    } else if (bid < 640) {
        int idx = (bid - 512) * 256 + t;      // exactly H2*H12
        g_f2h[idx] = f16pair(fc2_w[2 * idx], fc2_w[2 * idx + 1]);
    } else {
        if (t < H2) {
            float s = fc2_b[t];
            for (int h = 0; h < H1; h++) s = fmaf(fc2_w[t * H1 + h], fc1_b[h], s);
            g_b12[t] = s;
        } else if (t < H2 + C_OUT) {
            int co = t - H2;
            float inv = gamma[co] * rsqrtf(var[co] + 1e-5f);
            g_cb[co] = (conv_b[co] - mean[co]) * inv + beta[co];
        }
    }
}

// ---------------------------------------------------------------------------
// fc1 transpose + cvt: [h=512][f=3904] fp32 -> g_f1h [f][h/2] fp16x2.
// ---------------------------------------------------------------------------
__global__ void __launch_bounds__(256) f1t_kernel(const float* __restrict__ fc1_w) {
    __shared__ float s[64][33];
    int t  = threadIdx.x;
    int f0 = blockIdx.x * 32;
    int h0 = blockIdx.y * 64;
#pragma unroll
    for (int it = 0; it < 8; it++) {
        int idx = it * 256 + t;
        int hh = idx >> 5, ff = idx & 31;
        s[hh][ff] = fc1_w[(size_t)(h0 + hh) * FLAT + f0 + ff];
    }
    __syncthreads();
    int hb2 = blockIdx.y * 32;
#pragma unroll
    for (int it = 0; it < 4; it++) {
        int idx = it * 256 + t;
        int ff = idx >> 5, pi = idx & 31;
        g_f1h[(size_t)(f0 + ff) * H12 + hb2 + pi] =
            f16pair(s[2 * pi][ff], s[2 * pi + 1][ff]);
    }
}

// ---------------------------------------------------------------------------
// W12 = fc2 @ fc1 via mma.sync. M=128 j, N=32 f per block (grid 122), K=512.
// ---------------------------------------------------------------------------
__global__ void __launch_bounds__(256) w12mma_kernel() {
    __shared__ uint32_t asm_[H2 * 32];
    __shared__ uint32_t bsm_[32 * 32];

    int t = threadIdx.x, w = t >> 5, lane = t & 31;
    int mw = w;
    uint32_t as_addr = smem_u32(asm_);
    uint32_t bs_addr = smem_u32(bsm_);
    int f0 = blockIdx.x * 32;

    float acc[4][4];
#pragma unroll
    for (int nt = 0; nt < 4; nt++)
#pragma unroll
        for (int r = 0; r < 4; r++) acc[nt][r] = 0.f;

    int sub = lane >> 3, r8 = lane & 7;
    int arow = mw * 16 + (sub & 1) * 8 + r8;
    uint32_t akb   = (uint32_t)((sub >> 1) * 16);
    uint32_t abase = as_addr + (uint32_t)(arow * 128);
    uint32_t aswz  = (uint32_t)(r8 << 4);

    int btile = lane >> 3, brow = lane & 7;
    uint32_t bbase[2];
    uint32_t bkb  = (uint32_t)((btile & 1) * 16);
    uint32_t bswz = (uint32_t)(brow << 4);
#pragma unroll
    for (int p = 0; p < 2; p++) {
        int floc = (2 * p + (btile >> 1)) * 8 + brow;
        bbase[p] = bs_addr + (uint32_t)(floc * 128);
    }

    int wj = t >> 1, wh = t & 1;
    char* arowp = (char*)asm_ + wj * 128;
    uint32_t awz = (uint32_t)((wj & 7) << 4);
    int am = t >> 3, akg = t & 7;
    uint32_t bst = bs_addr + (uint32_t)(am * 128) +
                   (((uint32_t)(akg * 16)) ^ ((uint32_t)((am & 7) << 4)));

#pragma unroll 1
    for (int cc = 0; cc < 8; cc++) {
        __syncthreads();
        {
            const uint4* src = (const uint4*)(g_f2h + (size_t)wj * H12 + cc * 32 + wh * 16);
#pragma unroll
            for (int qq = 0; qq < 4; qq++) {
                uint4 v = src[qq];
                *(uint4*)(arowp + (((uint32_t)(wh * 64 + qq * 16)) ^ awz)) = v;
            }
        }
        {
            uint4 v = *(const uint4*)(g_f1h + (size_t)(f0 + am) * H12 + cc * 32 + akg * 4);
            *(uint4*)((char*)bsm_ + (bst - bs_addr)) = v;
        }
        __syncthreads();

#pragma unroll
        for (int ks = 0; ks < 4; ks++) {
            uint32_t af[4];
            ldsm4(af, abase + (((uint32_t)(ks * 32) + akb) ^ aswz));
            uint32_t bf[8];
#pragma unroll
            for (int p = 0; p < 2; p++)
                ldsm4(&bf[4 * p], bbase[p] + (((uint32_t)(ks * 32) + bkb) ^ bswz));
#pragma unroll
            for (int nt = 0; nt < 4; nt++) {
                int bi = 4 * (nt >> 1) + 2 * (nt & 1);
                hmma(acc[nt], af[0], af[1], af[2], af[3], bf[bi], bf[bi + 1]);
            }
        }
    }

    unsigned short* dst = (unsigned short*)g_w12h;
    int r = lane >> 2, c = lane & 3;
#pragma unroll
    for (int nt = 0; nt < 4; nt++) {
#pragma unroll
        for (int e = 0; e < 4; e++) {
            int f = f0 + nt * 8 + 2 * c + (e & 1);
            int j = mw * 16 + r + (e >> 1) * 8;
            int co = f / L_OUT;
            int l  = f - co * L_OUT;
            dst[(size_t)j * FLAT + l * 64 + co] = f16one(acc[nt][e]);
        }
    }
}

// ---------------------------------------------------------------------------
// Conv + BN + ReLU via mma.sync, cp.async double-buffered pipeline.
// Block: 256 thr / 8 warps, 4 batches (grid 512). Warp = batch (w>>1) x
// l-half (w&1): M=32 per warp (2 m16 tiles) x all 64 co.
// Static smem engineered to exactly 48KB; A-load indices clamped in-row.
// ---------------------------------------------------------------------------
#define XROWF 256                 // floats per (q,ci) smem row, no pad
__global__ void __launch_bounds__(256, 2) conv_mma_kernel(const float* __restrict__ x) {
    __shared__ float    xs[2][16 * XROWF];   // 2 x 16KB
    __shared__ uint32_t bsm[2][C_OUT * 32];  // 2 x 8KB  (total = 48KB exactly)

    int t = threadIdx.x, w = t >> 5, lane = t & 31;
    int q = w >> 1, half = w & 1;
    uint32_t xs_addr = smem_u32(xs);
    uint32_t bs_addr = smem_u32(bsm);

    float acc[2][8][4];
#pragma unroll
    for (int mt = 0; mt < 2; mt++)
#pragma unroll
        for (int nt = 0; nt < 8; nt++)
#pragma unroll
            for (int r = 0; r < 4; r++) acc[mt][nt][r] = 0.f;

    // ---- B ldmatrix addressing (within-buffer offsets) ----
    int btile = lane >> 3, brow = lane & 7;
    uint32_t bbase[4], bkb[4], bsw[4];
#pragma unroll
    for (int p = 0; p < 4; p++) {
        int co = (2 * p + (btile >> 1)) * 8 + brow;
        bbase[p] = (uint32_t)(co * 128);
        bkb[p]   = (uint32_t)((btile & 1) * 16);
        bsw[p]   = (uint32_t)((co & 7) << 4);
    }

    // ---- staging addressing: x = 4 cp.async/thread, B = 2 cp.async/thread --
    int xrow0 = t >> 6;              // base row 0..3 (i adds 4)
    int xcol  = (t & 63) * 16;       // byte offset within 1KB row
    uint32_t    xdst[4];
    const char* xsrc[4];
#pragma unroll
    for (int i = 0; i < 4; i++) {
        int row = i * 4 + xrow0;     // row = q*4 + ci
        int qi = row >> 2, ci = row & 3;
        xdst[i] = xs_addr + (uint32_t)(row * 1024 + xcol);
        xsrc[i] = (const char*)x + (size_t)(blockIdx.x * 4 + qi) * (C_IN * L_IN * 4)
                  + ci * 1024 + xcol;
    }
    int brw = t >> 3;
    int bg  = t & 7;
    uint32_t bd0 = bs_addr + (uint32_t)(brw * 128) + (((uint32_t)(bg * 16)) ^ ((uint32_t)((brw & 7) << 4)));
    uint32_t bd1 = bs_addr + (uint32_t)((brw + 32) * 128) + (((uint32_t)(bg * 16)) ^ ((uint32_t)(((brw + 32) & 7) << 4)));
    const char* bsrc0 = (const char*)g_wh + (size_t)brw * 8192 + bg * 16;
    const char* bsrc1 = bsrc0 + (size_t)32 * 8192;

#define STAGE(cc, buf) do {                                                     \
    uint32_t xb = (uint32_t)((buf) * (16 * XROWF * 4));                         \
    uint32_t bb = (uint32_t)((buf) * (C_OUT * 32 * 4));                         \
    size_t xo = (size_t)(cc) * 4096;                                            \
    size_t bo = (size_t)(cc) * 128;                                             \
    CP_ASYNC16(xdst[0] + xb, xsrc[0] + xo);                                     \
    CP_ASYNC16(xdst[1] + xb, xsrc[1] + xo);                                     \
    CP_ASYNC16(xdst[2] + xb, xsrc[2] + xo);                                     \
    CP_ASYNC16(xdst[3] + xb, xsrc[3] + xo);                                     \
    CP_ASYNC16(bd0 + bb, bsrc0 + bo);                                           \
    CP_ASYNC16(bd1 + bb, bsrc1 + bo);                                           \
} while (0)

    STAGE(0, 0);
    CP_COMMIT();

    int c = lane & 3, rq = lane >> 2;
    int lbase = half * 32;

#pragma unroll 1
    for (int cc = 0; cc < NCHUNK; cc++) {
        __syncthreads();
        if (cc < NCHUNK - 1) STAGE(cc + 1, (cc + 1) & 1);
        CP_COMMIT();
        CP_WAIT1();
        __syncthreads();

        int buf = cc & 1;
        uint32_t bbuf = bs_addr + (uint32_t)(buf * (C_OUT * 32 * 4));
        const float* xbuf = &xs[buf][q * 4 * XROWF];

#pragma unroll
        for (int ks = 0; ks < 4; ks++) {
            uint32_t bfr[16];
#pragma unroll
            for (int p = 0; p < 4; p++) {
                uint32_t addr = bbuf + bbase[p] + (((uint32_t)(ks * 32) + bkb[p]) ^ bsw[p]);
                ldsm4(&bfr[4 * p], addr);
            }
            const float2* xp = (const float2*)(xbuf + ks * XROWF);
#pragma unroll
            for (int mt = 0; mt < 2; mt++) {
                int e0 = 2 * (lbase + mt * 16 + rq) + c;
                // Clamp to stay in-row: valid (l<61) indices never exceed 127,
                // so clamping only changes garbage destined for masked rows.
                int i0 = min(e0, 127);
                int i1 = min(e0 + 16, 127);
                int i2 = min(e0 + 4, 127);
                int i3 = min(e0 + 20, 127);
                float2 v0 = xp[i0];
                float2 v1 = xp[i1];
                float2 v2 = xp[i2];
                float2 v3 = xp[i3];
                uint32_t a0 = f16pair(v0.x, v0.y);
                uint32_t a1 = f16pair(v1.x, v1.y);
                uint32_t a2 = f16pair(v2.x, v2.y);
                uint32_t a3 = f16pair(v3.x, v3.y);
#pragma unroll
                for (int nt = 0; nt < 8; nt++) {
                    int bi = 4 * (nt >> 1) + 2 * (nt & 1);
                    hmma(acc[mt][nt], a0, a1, a2, a3, bfr[bi], bfr[bi + 1]);
                }
            }
        }
    }

    // ---- epilogue: bias + relu -> fp16 pairs -> g_acth[b][(l*64+co)/2] ----
    int b = blockIdx.x * 4 + q;
    unsigned* dst = g_acth + (size_t)b * FLAT2;
#pragma unroll
    for (int mt = 0; mt < 2; mt++) {
        int l1 = lbase + mt * 16 + rq;
        int l2 = l1 + 8;
#pragma unroll
        for (int nt = 0; nt < 8; nt++) {
            int co0 = nt * 8 + 2 * c;
            float cb0 = g_cb[co0], cb1 = g_cb[co0 + 1];
            if (l1 < L_OUT) {
                float v0 = acc[mt][nt][0] + cb0;
                float v1 = acc[mt][nt][1] + cb1;
                dst[l1 * 32 + nt * 4 + c] = f16pair(v0 > 0.f ? v0 : 0.f, v1 > 0.f ? v1 : 0.f);
            }
            if (l2 < L_OUT) {
                float v2 = acc[mt][nt][2] + cb0;
                float v3 = acc[mt][nt][3] + cb1;
                dst[l2 * 32 + nt * 4 + c] = f16pair(v2 > 0.f ? v2 : 0.f, v3 > 0.f ? v3 : 0.f);
            }
        }
    }
#undef STAGE
}

// ---------------------------------------------------------------------------
// feats = act @ W12^T + b12 via mma.sync, fused parabit heads -> out.
// M=16 batches per block (grid 128). Warp w -> j-slice [w*16, w*16+16).
// ---------------------------------------------------------------------------
__global__ void __launch_bounds__(256) feats_mma_kernel(const float* __restrict__ bit_w,
                                                        const float* __restrict__ bit_b,
                                                        float* __restrict__ out) {
    __shared__ uint32_t as_[16 * 32];
    __shared__ uint32_t ws_[H2 * 32];
    __shared__ float sb12[H2], sbw[H2 * 2], sbb[H2 * 2];

    int t = threadIdx.x, w = t >> 5, lane = t & 31;
    if (t < H2) sb12[t] = g_b12[t];
    if (t < H2 * 2) { sbw[t] = bit_w[t]; sbb[t] = bit_b[t]; }
    uint32_t as_addr = smem_u32(as_);
    uint32_t ws_addr = smem_u32(ws_);

    int b0 = blockIdx.x * 16;

    float acc[2][4];
#pragma unroll
    for (int nt = 0; nt < 2; nt++)
#pragma unroll
        for (int r = 0; r < 4; r++) acc[nt][r] = 0.f;

    int sub = lane >> 3, r8 = lane & 7;
    int arow = (sub & 1) * 8 + r8;
    uint32_t akb   = (uint32_t)((sub >> 1) * 16);
    uint32_t abase = as_addr + (uint32_t)(arow * 128);
    uint32_t aswz  = (uint32_t)(r8 << 4);

    int g = lane >> 3, brow = lane & 7;
    int bj  = w * 16 + (g >> 1) * 8 + brow;
    uint32_t bkb  = (uint32_t)((g & 1) * 16);
    uint32_t bbase = ws_addr + (uint32_t)(bj * 128);
    uint32_t bswz = (uint32_t)(brow << 4);

    int am = t >> 3, akg = t & 7;
    uint32_t ast = as_addr + (uint32_t)(am * 128) +
                   (((uint32_t)(akg * 16)) ^ ((uint32_t)((am & 7) << 4)));
    int wj = t >> 1, wh = t & 1;
    char* wrow = (char*)ws_ + wj * 128;
    uint32_t wswz = (uint32_t)((wj & 7) << 4);

#pragma unroll 1
    for (int cc = 0; cc < 61; cc++) {
        __syncthreads();
        if (am < 16) {
            uint4 v = *(const uint4*)(g_acth + (size_t)(b0 + am) * FLAT2 + cc * 32 + akg * 4);
            *(uint4*)((char*)as_ + (ast - as_addr)) = v;
        }
        {
            const uint4* src = (const uint4*)(g_w12h + (size_t)wj * FLAT2 + cc * 32 + wh * 16);
#pragma unroll
            for (int qq = 0; qq < 4; qq++) {
                uint4 v = src[qq];
                *(uint4*)(wrow + (((uint32_t)(wh * 64 + qq * 16)) ^ wswz)) = v;
            }
        }
        __syncthreads();

#pragma unroll
        for (int ks = 0; ks < 4; ks++) {
            uint32_t af[4];
            ldsm4(af, abase + (((uint32_t)(ks * 32) + akb) ^ aswz));
            uint32_t bf[4];
            ldsm4(bf, bbase + (((uint32_t)(ks * 32) + bkb) ^ bswz));
#pragma unroll
            for (int nt = 0; nt < 2; nt++)
                hmma(acc[nt], af[0], af[1], af[2], af[3], bf[2 * nt], bf[2 * nt + 1]);
        }
    }

    int r = lane >> 2, c = lane & 3;
#pragma unroll
    for (int nt = 0; nt < 2; nt++) {
        int j0 = w * 16 + nt * 8 + 2 * c;
        float bj0 = sb12[j0], bj1 = sb12[j0 + 1];
        float bw00 = sbw[j0 * 2], bw01 = sbw[j0 * 2 + 1];
        float bw10 = sbw[j0 * 2 + 2], bw11 = sbw[j0 * 2 + 3];
        float bb00 = sbb[j0 * 2], bb01 = sbb[j0 * 2 + 1];
        float bb10 = sbb[j0 * 2 + 2], bb11 = sbb[j0 * 2 + 3];
        {
            int b = b0 + r;
            float f0 = acc[nt][0] + bj0;
            float f1 = acc[nt][1] + bj1;
            float4 o = make_float4(fmaf(f0, bw00, bb00), fmaf(f0, bw01, bb01),
                                   fmaf(f1, bw10, bb10), fmaf(f1, bw11, bb11));
            *(float4*)(out + ((size_t)b * H2 + j0) * 2) = o;
        }
        {
            int b = b0 + r + 8;
            float f2 = acc[nt][2] + bj0;
            float f3 = acc[nt][3] + bj1;
            float4 o = make_float4(fmaf(f2, bw00, bb00), fmaf(f2, bw01, bb01),
                                   fmaf(f3, bw10, bb10), fmaf(f3, bw11, bb11));
            *(float4*)(out + ((size_t)b * H2 + j0) * 2) = o;
        }
    }
}

// ---------------------------------------------------------------------------
extern "C" void kernel_launch(void* const* d_in, const int* in_sizes, int n_in,
                              void* d_out, int out_size) {
    const float* x      = (const float*)d_in[0];
    const float* conv_w = (const float*)d_in[1];
    const float* conv_b = (const float*)d_in[2];
    const float* gamma  = (const float*)d_in[3];
    const float* beta   = (const float*)d_in[4];
    const float* mean   = (const float*)d_in[5];
    const float* var    = (const float*)d_in[6];
    const float* fc1_w  = (const float*)d_in[7];
    const float* fc1_b  = (const float*)d_in[8];
    const float* fc2_w  = (const float*)d_in[9];
    const float* fc2_b  = (const float*)d_in[10];
    const float* bit_w  = (const float*)d_in[11];
    const float* bit_b  = (const float*)d_in[12];
    float* out = (float*)d_out;

    static cudaStream_t s2 = nullptr;
    static cudaEvent_t evFork = nullptr, evJoin = nullptr;
    if (!s2) {
        cudaStreamCreateWithFlags(&s2, cudaStreamNonBlocking);
        cudaEventCreateWithFlags(&evFork, cudaEventDisableTiming);
        cudaEventCreateWithFlags(&evJoin, cudaEventDisableTiming);
    }

    // main stream: prep_all -> conv  |  s2: f1t -> w12mma (parallel to conv)
    prep_all_kernel<<<641, 256>>>(conv_w, conv_b, gamma, beta, mean, var,
                                  fc1_b, fc2_w, fc2_b);
    cudaEventRecord(evFork, 0);
    cudaStreamWaitEvent(s2, evFork, 0);
    f1t_kernel<<<dim3(FLAT / 32, 8), 256, 0, s2>>>(fc1_w);
    w12mma_kernel<<<FLAT / 32, 256, 0, s2>>>();
    cudaEventRecord(evJoin, s2);

    conv_mma_kernel<<<BB / 4, 256>>>(x);
    cudaStreamWaitEvent((cudaStream_t)0, evJoin, 0);
    feats_mma_kernel<<<BB / 16, 256>>>(bit_w, bit_b, out);
}

// round 12
// speedup vs baseline: 9.9488x; 1.0754x over previous
#include <cuda_runtime.h>
#include <cstdint>

#define BB 2048
#define C_IN 256
#define L_IN 256
#define C_OUT 64
#define KW 16
#define L_OUT 61
#define FLAT 3904    // 64*61
#define FLAT2 1952   // FLAT/2 (f16x2 pairs)
#define H1 512
#define H12 256      // H1/2 pairs
#define H2 128
#define KTOT 4096    // C_IN*KW
#define NCHUNK 64    // conv K chunks of 64 (4 ci each)

// ---------------- scratch (static device arrays; no allocation) -------------
__device__ unsigned g_acth[(size_t)BB * FLAT2];   // act fp16x2, [b][(l*64+co)/2]
__device__ unsigned g_w12h[H2 * FLAT2];           // W12 fp16x2, [j][(l*64+co)/2]
__device__ float    g_b12[H2];
__device__ float    g_cb[C_OUT];
__device__ unsigned g_wh[C_OUT * (KTOT / 2)];     // conv weights fp16x2, [co][K/2]
__device__ unsigned g_f1h[(size_t)FLAT * H12];    // fc1^T fp16x2, [f][h/2]
__device__ unsigned g_f2h[H2 * H12];              // fc2 fp16x2, [j][h/2]

// ---------------- PTX helpers ----------------------------------------------
__device__ __forceinline__ uint32_t smem_u32(const void* p) {
    uint32_t a;
    asm("{ .reg .u64 t; cvta.to.shared.u64 t, %1; cvt.u32.u64 %0, t; }"
        : "=r"(a) : "l"(p));
    return a;
}
__device__ __forceinline__ uint32_t f16pair(float lo, float hi) {
    uint32_t r;
    asm("cvt.rn.f16x2.f32 %0, %1, %2;" : "=r"(r) : "f"(hi), "f"(lo));
    return r;
}
__device__ __forceinline__ unsigned short f16one(float v) {
    unsigned short r;
    asm("cvt.rn.f16.f32 %0, %1;" : "=h"(r) : "f"(v));
    return r;
}
__device__ __forceinline__ uint32_t lds32(uint32_t addr) {
    uint32_t v;
    asm volatile("ld.shared.b32 %0, [%1];" : "=r"(v) : "r"(addr));
    return v;
}
__device__ __forceinline__ void sts64(uint32_t addr, uint32_t v0, uint32_t v1) {
    asm volatile("st.shared.v2.b32 [%0], {%1, %2};" :: "r"(addr), "r"(v0), "r"(v1));
}
__device__ __forceinline__ void ldsm4(uint32_t* r, uint32_t addr) {
    asm volatile("ldmatrix.sync.aligned.m8n8.x4.shared.b16 {%0,%1,%2,%3}, [%4];"
                 : "=r"(r[0]), "=r"(r[1]), "=r"(r[2]), "=r"(r[3]) : "r"(addr));
}
__device__ __forceinline__ void hmma(float* d, uint32_t a0, uint32_t a1,
                                     uint32_t a2, uint32_t a3,
                                     uint32_t b0, uint32_t b1) {
    asm volatile("mma.sync.aligned.m16n8k16.row.col.f32.f16.f16.f32 "
                 "{%0,%1,%2,%3}, {%4,%5,%6,%7}, {%8,%9}, {%0,%1,%2,%3};"
                 : "+f"(d[0]), "+f"(d[1]), "+f"(d[2]), "+f"(d[3])
                 : "r"(a0), "r"(a1), "r"(a2), "r"(a3), "r"(b0), "r"(b1));
}
#define CP_ASYNC16(dst, src) \
    asm volatile("cp.async.cg.shared.global [%0], [%1], 16;" \
                 :: "r"(dst), "l"(src) : "memory")
#define CP_COMMIT() asm volatile("cp.async.commit_group;" ::: "memory")
#define CP_WAIT1()  asm volatile("cp.async.wait_group 1;" ::: "memory")

// ---------------------------------------------------------------------------
// prep_all: one launch for all weight preprocessing.
// ---------------------------------------------------------------------------
__global__ void __launch_bounds__(256) prep_all_kernel(
        const float* __restrict__ conv_w, const float* __restrict__ conv_b,
        const float* __restrict__ gamma,  const float* __restrict__ beta,
        const float* __restrict__ mean,   const float* __restrict__ var,
        const float* __restrict__ fc1_b,  const float* __restrict__ fc2_w,
        const float* __restrict__ fc2_b) {
    int bid = blockIdx.x, t = threadIdx.x;
    if (bid < 512) {
        int idx = bid * 256 + t;              // exactly C_OUT*(KTOT/2)
        int co = idx >> 11;
        int kg = (idx & 2047) * 2;
        int ci = kg >> 4, k = kg & 15;
        float inv = gamma[co] * rsqrtf(var[co] + 1e-5f);
        const float* src = conv_w + ((size_t)co * C_IN + ci) * KW + k;
        g_wh[idx] = f16pair(src[0] * inv, src[1] * inv);
    } else if (bid < 640) {
        int idx = (bid - 512) * 256 + t;      // exactly H2*H12
        g_f2h[idx] = f16pair(fc2_w[2 * idx], fc2_w[2 * idx + 1]);
    } else {
        if (t < H2) {
            float s = fc2_b[t];
            for (int h = 0; h < H1; h++) s = fmaf(fc2_w[t * H1 + h], fc1_b[h], s);
            g_b12[t] = s;
        } else if (t < H2 + C_OUT) {
            int co = t - H2;
            float inv = gamma[co] * rsqrtf(var[co] + 1e-5f);
            g_cb[co] = (conv_b[co] - mean[co]) * inv + beta[co];
        }
    }
}

// ---------------------------------------------------------------------------
// fc1 transpose + cvt: [h=512][f=3904] fp32 -> g_f1h [f][h/2] fp16x2.
// ---------------------------------------------------------------------------
__global__ void __launch_bounds__(256) f1t_kernel(const float* __restrict__ fc1_w) {
    __shared__ float s[64][33];
    int t  = threadIdx.x;
    int f0 = blockIdx.x * 32;
    int h0 = blockIdx.y * 64;
#pragma unroll
    for (int it = 0; it < 8; it++) {
        int idx = it * 256 + t;
        int hh = idx >> 5, ff = idx & 31;
        s[hh][ff] = fc1_w[(size_t)(h0 + hh) * FLAT + f0 + ff];
    }
    __syncthreads();
    int hb2 = blockIdx.y * 32;
#pragma unroll
    for (int it = 0; it < 4; it++) {
        int idx = it * 256 + t;
        int ff = idx >> 5, pi = idx & 31;
        g_f1h[(size_t)(f0 + ff) * H12 + hb2 + pi] =
            f16pair(s[2 * pi][ff], s[2 * pi + 1][ff]);
    }
}

// ---------------------------------------------------------------------------
// W12 = fc2 @ fc1 via mma.sync. M=128 j, N=32 f per block (grid 122), K=512.
// ---------------------------------------------------------------------------
__global__ void __launch_bounds__(256) w12mma_kernel() {
    __shared__ uint32_t asm_[H2 * 32];
    __shared__ uint32_t bsm_[32 * 32];

    int t = threadIdx.x, w = t >> 5, lane = t & 31;
    int mw = w;
    uint32_t as_addr = smem_u32(asm_);
    uint32_t bs_addr = smem_u32(bsm_);
    int f0 = blockIdx.x * 32;

    float acc[4][4];
#pragma unroll
    for (int nt = 0; nt < 4; nt++)
#pragma unroll
        for (int r = 0; r < 4; r++) acc[nt][r] = 0.f;

    int sub = lane >> 3, r8 = lane & 7;
    int arow = mw * 16 + (sub & 1) * 8 + r8;
    uint32_t akb   = (uint32_t)((sub >> 1) * 16);
    uint32_t abase = as_addr + (uint32_t)(arow * 128);
    uint32_t aswz  = (uint32_t)(r8 << 4);

    int btile = lane >> 3, brow = lane & 7;
    uint32_t bbase[2];
    uint32_t bkb  = (uint32_t)((btile & 1) * 16);
    uint32_t bswz = (uint32_t)(brow << 4);
#pragma unroll
    for (int p = 0; p < 2; p++) {
        int floc = (2 * p + (btile >> 1)) * 8 + brow;
        bbase[p] = bs_addr + (uint32_t)(floc * 128);
    }

    int wj = t >> 1, wh = t & 1;
    char* arowp = (char*)asm_ + wj * 128;
    uint32_t awz = (uint32_t)((wj & 7) << 4);
    int am = t >> 3, akg = t & 7;
    uint32_t bst = bs_addr + (uint32_t)(am * 128) +
                   (((uint32_t)(akg * 16)) ^ ((uint32_t)((am & 7) << 4)));

#pragma unroll 1
    for (int cc = 0; cc < 8; cc++) {
        __syncthreads();
        {
            const uint4* src = (const uint4*)(g_f2h + (size_t)wj * H12 + cc * 32 + wh * 16);
#pragma unroll
            for (int qq = 0; qq < 4; qq++) {
                uint4 v = src[qq];
                *(uint4*)(arowp + (((uint32_t)(wh * 64 + qq * 16)) ^ awz)) = v;
            }
        }
        {
            uint4 v = *(const uint4*)(g_f1h + (size_t)(f0 + am) * H12 + cc * 32 + akg * 4);
            *(uint4*)((char*)bsm_ + (bst - bs_addr)) = v;
        }
        __syncthreads();

#pragma unroll
        for (int ks = 0; ks < 4; ks++) {
            uint32_t af[4];
            ldsm4(af, abase + (((uint32_t)(ks * 32) + akb) ^ aswz));
            uint32_t bf[8];
#pragma unroll
            for (int p = 0; p < 2; p++)
                ldsm4(&bf[4 * p], bbase[p] + (((uint32_t)(ks * 32) + bkb) ^ bswz));
#pragma unroll
            for (int nt = 0; nt < 4; nt++) {
                int bi = 4 * (nt >> 1) + 2 * (nt & 1);
                hmma(acc[nt], af[0], af[1], af[2], af[3], bf[bi], bf[bi + 1]);
            }
        }
    }

    unsigned short* dst = (unsigned short*)g_w12h;
    int r = lane >> 2, c = lane & 3;
#pragma unroll
    for (int nt = 0; nt < 4; nt++) {
#pragma unroll
        for (int e = 0; e < 4; e++) {
            int f = f0 + nt * 8 + 2 * c + (e & 1);
            int j = mw * 16 + r + (e >> 1) * 8;
            int co = f / L_OUT;
            int l  = f - co * L_OUT;
            dst[(size_t)j * FLAT + l * 64 + co] = f16one(acc[nt][e]);
        }
    }
}

// ---------------------------------------------------------------------------
// Conv + BN + ReLU via mma.sync. x staged to smem as fp16 (converted once at
// staging, LDG reg-buffered); weights double-buffered via cp.async.
// Block: 256 thr / 8 warps, 4 batches (grid 512). Warp = batch (w>>1) x
// l-half (w&1): M=32 per warp (2 m16 tiles) x all 64 co.
// Inner loop: 4 ldsm4 (B) + 8 bare LDS.32 (A, fp16x2 fragments) + 16 HMMA.
// ---------------------------------------------------------------------------
__global__ void __launch_bounds__(256, 2) conv_mma_kernel(const float* __restrict__ x) {
    __shared__ unsigned xh[2][16 * 128];     // fp16x2 x, 2 x 8KB: row=(q*4+ci), 128 uint
    __shared__ uint32_t bsm[2][C_OUT * 32];  // fp16x2 weights swizzled, 2 x 8KB

    int t = threadIdx.x, w = t >> 5, lane = t & 31;
    int q = w >> 1, half = w & 1;
    uint32_t xh_addr = smem_u32(xh);
    uint32_t bs_addr = smem_u32(bsm);

    float acc[2][8][4];
#pragma unroll
    for (int mt = 0; mt < 2; mt++)
#pragma unroll
        for (int nt = 0; nt < 8; nt++)
#pragma unroll
            for (int r = 0; r < 4; r++) acc[mt][nt][r] = 0.f;

    // ---- B ldmatrix addressing (within-buffer offsets) ----
    int btile = lane >> 3, brow = lane & 7;
    uint32_t bbase[4], bkb[4], bsw[4];
#pragma unroll
    for (int p = 0; p < 4; p++) {
        int co = (2 * p + (btile >> 1)) * 8 + brow;
        bbase[p] = (uint32_t)(co * 128);
        bkb[p]   = (uint32_t)((btile & 1) * 16);
        bsw[p]   = (uint32_t)((co & 7) << 4);
    }

    // ---- A addressing: byte offset within (q,ks) fp16 row (512B) ----
    int c = lane & 3, rq = lane >> 2;
    int lbase = half * 32;
    uint32_t aoff = (uint32_t)(8 * (lbase + rq) + 4 * c);

    // ---- x staging: thread owns row r=(t>>4) of 16, quarter lane16=t&15 ----
    int xr = t >> 4, lane16 = t & 15;
    int xq = xr >> 2, xci = xr & 3;
    const float4* xsrc = (const float4*)x
        + ((size_t)(blockIdx.x * 4 + xq) * (C_IN * L_IN) + xci * L_IN) / 4 + lane16;
    uint32_t xsts = xh_addr + (uint32_t)(xr * 512 + lane16 * 8);

    // ---- B staging via cp.async (unchanged pattern) ----
    int brw = t >> 3;
    int bg  = t & 7;
    uint32_t bd0 = bs_addr + (uint32_t)(brw * 128) + (((uint32_t)(bg * 16)) ^ ((uint32_t)((brw & 7) << 4)));
    uint32_t bd1 = bs_addr + (uint32_t)((brw + 32) * 128) + (((uint32_t)(bg * 16)) ^ ((uint32_t)(((brw + 32) & 7) << 4)));
    const char* bsrc0 = (const char*)g_wh + (size_t)brw * 8192 + bg * 16;
    const char* bsrc1 = bsrc0 + (size_t)32 * 8192;

    // preload chunk 0
    float4 rx0 = xsrc[0], rx1 = xsrc[16], rx2 = xsrc[32], rx3 = xsrc[48];
    CP_ASYNC16(bd0, bsrc0);
    CP_ASYNC16(bd1, bsrc1);
    CP_COMMIT();

#pragma unroll 1
    for (int cc = 0; cc < NCHUNK; cc++) {
        __syncthreads();                       // prior compute done; buffers free
        // convert + store this chunk's x (values identical to direct cvt)
        {
            uint32_t xb = xsts + (uint32_t)((cc & 1) * 8192);
            sts64(xb,        f16pair(rx0.x, rx0.y), f16pair(rx0.z, rx0.w));
            sts64(xb + 128,  f16pair(rx1.x, rx1.y), f16pair(rx1.z, rx1.w));
            sts64(xb + 256,  f16pair(rx2.x, rx2.y), f16pair(rx2.z, rx2.w));
            sts64(xb + 384,  f16pair(rx3.x, rx3.y), f16pair(rx3.z, rx3.w));
        }
        if (cc < NCHUNK - 1) {                 // prefetch next chunk
            const float4* nsrc = xsrc + (size_t)(cc + 1) * 256;
            rx0 = nsrc[0]; rx1 = nsrc[16]; rx2 = nsrc[32]; rx3 = nsrc[48];
            uint32_t bb = (uint32_t)(((cc + 1) & 1) * (C_OUT * 32 * 4));
            size_t bo = (size_t)(cc + 1) * 128;
            CP_ASYNC16(bd0 + bb, bsrc0 + bo);
            CP_ASYNC16(bd1 + bb, bsrc1 + bo);
        }
        CP_COMMIT();
        CP_WAIT1();                            // B(cc) landed
        __syncthreads();                       // x stores visible to all warps

        int buf = cc & 1;
        uint32_t bbuf = bs_addr + (uint32_t)(buf * (C_OUT * 32 * 4));
        uint32_t xchunk = xh_addr + (uint32_t)(buf * 8192) + (uint32_t)(q * 4 * 512);

#pragma unroll
        for (int ks = 0; ks < 4; ks++) {
            uint32_t bfr[16];
#pragma unroll
            for (int p = 0; p < 4; p++) {
                uint32_t addr = bbuf + bbase[p] + (((uint32_t)(ks * 32) + bkb[p]) ^ bsw[p]);
                ldsm4(&bfr[4 * p], addr);
            }
            uint32_t xrow = xchunk + (uint32_t)(ks * 512) + aoff;
#pragma unroll
            for (int mt = 0; mt < 2; mt++) {
                uint32_t base = xrow + (uint32_t)(mt * 128);
                uint32_t a0 = lds32(base);         // rows 0-7,  k 2c..2c+1
                uint32_t a1 = lds32(base + 64);    // rows 8-15, k 2c..2c+1
                uint32_t a2 = lds32(base + 16);    // rows 0-7,  k 8+2c
                uint32_t a3 = lds32(base + 80);    // rows 8-15, k 8+2c
#pragma unroll
                for (int nt = 0; nt < 8; nt++) {
                    int bi = 4 * (nt >> 1) + 2 * (nt & 1);
                    hmma(acc[mt][nt], a0, a1, a2, a3, bfr[bi], bfr[bi + 1]);
                }
            }
        }
    }

    // ---- epilogue: bias + relu -> fp16 pairs -> g_acth[b][(l*64+co)/2] ----
    int b = blockIdx.x * 4 + q;
    unsigned* dst = g_acth + (size_t)b * FLAT2;
#pragma unroll
    for (int mt = 0; mt < 2; mt++) {
        int l1 = lbase + mt * 16 + rq;
        int l2 = l1 + 8;
#pragma unroll
        for (int nt = 0; nt < 8; nt++) {
            int co0 = nt * 8 + 2 * c;
            float cb0 = g_cb[co0], cb1 = g_cb[co0 + 1];
            if (l1 < L_OUT) {
                float v0 = acc[mt][nt][0] + cb0;
                float v1 = acc[mt][nt][1] + cb1;
                dst[l1 * 32 + nt * 4 + c] = f16pair(v0 > 0.f ? v0 : 0.f, v1 > 0.f ? v1 : 0.f);
            }
            if (l2 < L_OUT) {
                float v2 = acc[mt][nt][2] + cb0;
                float v3 = acc[mt][nt][3] + cb1;
                dst[l2 * 32 + nt * 4 + c] = f16pair(v2 > 0.f ? v2 : 0.f, v3 > 0.f ? v3 : 0.f);
            }
        }
    }
}

// ---------------------------------------------------------------------------
// feats = act @ W12^T + b12 via mma.sync, fused parabit heads -> out.
// ---------------------------------------------------------------------------
__global__ void __launch_bounds__(256) feats_mma_kernel(const float* __restrict__ bit_w,
                                                        const float* __restrict__ bit_b,
                                                        float* __restrict__ out) {
    __shared__ uint32_t as_[16 * 32];
    __shared__ uint32_t ws_[H2 * 32];
    __shared__ float sb12[H2], sbw[H2 * 2], sbb[H2 * 2];

    int t = threadIdx.x, w = t >> 5, lane = t & 31;
    if (t < H2) sb12[t] = g_b12[t];
    if (t < H2 * 2) { sbw[t] = bit_w[t]; sbb[t] = bit_b[t]; }
    uint32_t as_addr = smem_u32(as_);
    uint32_t ws_addr = smem_u32(ws_);

    int b0 = blockIdx.x * 16;

    float acc[2][4];
#pragma unroll
    for (int nt = 0; nt < 2; nt++)
#pragma unroll
        for (int r = 0; r < 4; r++) acc[nt][r] = 0.f;

    int sub = lane >> 3, r8 = lane & 7;
    int arow = (sub & 1) * 8 + r8;
    uint32_t akb   = (uint32_t)((sub >> 1) * 16);
    uint32_t abase = as_addr + (uint32_t)(arow * 128);
    uint32_t aswz  = (uint32_t)(r8 << 4);

    int g = lane >> 3, brow = lane & 7;
    int bj  = w * 16 + (g >> 1) * 8 + brow;
    uint32_t bkb  = (uint32_t)((g & 1) * 16);
    uint32_t bbase = ws_addr + (uint32_t)(bj * 128);
    uint32_t bswz = (uint32_t)(brow << 4);

    int am = t >> 3, akg = t & 7;
    uint32_t ast = as_addr + (uint32_t)(am * 128) +
                   (((uint32_t)(akg * 16)) ^ ((uint32_t)((am & 7) << 4)));
    int wj = t >> 1, wh = t & 1;
    char* wrow = (char*)ws_ + wj * 128;
    uint32_t wswz = (uint32_t)((wj & 7) << 4);

#pragma unroll 1
    for (int cc = 0; cc < 61; cc++) {
        __syncthreads();
        if (am < 16) {
            uint4 v = *(const uint4*)(g_acth + (size_t)(b0 + am) * FLAT2 + cc * 32 + akg * 4);
            *(uint4*)((char*)as_ + (ast - as_addr)) = v;
        }
        {
            const uint4* src = (const uint4*)(g_w12h + (size_t)wj * FLAT2 + cc * 32 + wh * 16);
#pragma unroll
            for (int qq = 0; qq < 4; qq++) {
                uint4 v = src[qq];
                *(uint4*)(wrow + (((uint32_t)(wh * 64 + qq * 16)) ^ wswz)) = v;
            }
        }
        __syncthreads();

#pragma unroll
        for (int ks = 0; ks < 4; ks++) {
            uint32_t af[4];
            ldsm4(af, abase + (((uint32_t)(ks * 32) + akb) ^ aswz));
            uint32_t bf[4];
            ldsm4(bf, bbase + (((uint32_t)(ks * 32) + bkb) ^ bswz));
#pragma unroll
            for (int nt = 0; nt < 2; nt++)
                hmma(acc[nt], af[0], af[1], af[2], af[3], bf[2 * nt], bf[2 * nt + 1]);
        }
    }

    int r = lane >> 2, c = lane & 3;
#pragma unroll
    for (int nt = 0; nt < 2; nt++) {
        int j0 = w * 16 + nt * 8 + 2 * c;
        float bj0 = sb12[j0], bj1 = sb12[j0 + 1];
        float bw00 = sbw[j0 * 2], bw01 = sbw[j0 * 2 + 1];
        float bw10 = sbw[j0 * 2 + 2], bw11 = sbw[j0 * 2 + 3];
        float bb00 = sbb[j0 * 2], bb01 = sbb[j0 * 2 + 1];
        float bb10 = sbb[j0 * 2 + 2], bb11 = sbb[j0 * 2 + 3];
        {
            int b = b0 + r;
            float f0 = acc[nt][0] + bj0;
            float f1 = acc[nt][1] + bj1;
            float4 o = make_float4(fmaf(f0, bw00, bb00), fmaf(f0, bw01, bb01),
                                   fmaf(f1, bw10, bb10), fmaf(f1, bw11, bb11));
            *(float4*)(out + ((size_t)b * H2 + j0) * 2) = o;
        }
        {
            int b = b0 + r + 8;
            float f2 = acc[nt][2] + bj0;
            float f3 = acc[nt][3] + bj1;
            float4 o = make_float4(fmaf(f2, bw00, bb00), fmaf(f2, bw01, bb01),
                                   fmaf(f3, bw10, bb10), fmaf(f3, bw11, bb11));
            *(float4*)(out + ((size_t)b * H2 + j0) * 2) = o;
        }
    }
}

// ---------------------------------------------------------------------------
extern "C" void kernel_launch(void* const* d_in, const int* in_sizes, int n_in,
                              void* d_out, int out_size) {
    const float* x      = (const float*)d_in[0];
    const float* conv_w = (const float*)d_in[1];
    const float* conv_b = (const float*)d_in[2];
    const float* gamma  = (const float*)d_in[3];
    const float* beta   = (const float*)d_in[4];
    const float* mean   = (const float*)d_in[5];
    const float* var    = (const float*)d_in[6];
    const float* fc1_w  = (const float*)d_in[7];
    const float* fc1_b  = (const float*)d_in[8];
    const float* fc2_w  = (const float*)d_in[9];
    const float* fc2_b  = (const float*)d_in[10];
    const float* bit_w  = (const float*)d_in[11];
    const float* bit_b  = (const float*)d_in[12];
    float* out = (float*)d_out;

    static cudaStream_t s2 = nullptr;
    static cudaEvent_t evFork = nullptr, evJoin = nullptr;
    if (!s2) {
        cudaStreamCreateWithFlags(&s2, cudaStreamNonBlocking);
        cudaEventCreateWithFlags(&evFork, cudaEventDisableTiming);
        cudaEventCreateWithFlags(&evJoin, cudaEventDisableTiming);
    }

    // main stream: prep_all -> conv  |  s2: f1t -> w12mma (parallel to conv)
    prep_all_kernel<<<641, 256>>>(conv_w, conv_b, gamma, beta, mean, var,
                                  fc1_b, fc2_w, fc2_b);
    cudaEventRecord(evFork, 0);
    cudaStreamWaitEvent(s2, evFork, 0);
    f1t_kernel<<<dim3(FLAT / 32, 8), 256, 0, s2>>>(fc1_w);
    w12mma_kernel<<<FLAT / 32, 256, 0, s2>>>();
    cudaEventRecord(evJoin, s2);

    conv_mma_kernel<<<BB / 4, 256>>>(x);
    cudaStreamWaitEvent((cudaStream_t)0, evJoin, 0);
    feats_mma_kernel<<<BB / 16, 256>>>(bit_w, bit_b, out);
}